// round 12
// baseline (speedup 1.0000x reference)
#include <cuda_runtime.h>
#include <cuda_bf16.h>
#include <math.h>
#include <stdint.h>

// Problem constants
#define Bx   1024
#define Lx   200
#define Dx   128
#define Hx   4
#define DKx  32
#define FFx  512
#define NLx  2
#define NT   (Bx*Lx)          // 204800 tokens
#define FC_SPLIT 32

// ---------------------------------------------------------------------------
// Device-global scratch (allocation-free rule).
// ---------------------------------------------------------------------------
__device__ float g_x  [(size_t)NT * Dx];    // residual stream (fp32)
__device__ float g_q  [(size_t)NT * Dx];
__device__ float g_k  [(size_t)NT * Dx];
__device__ float g_v  [(size_t)NT * Dx];
__device__ float g_fcp[(size_t)FC_SPLIT * Bx * Dx];

// bf16 hi/lo activation planes
__device__ __nv_bfloat16 g_ah[(size_t)NT * Dx],  g_al[(size_t)NT * Dx];   // LN out
__device__ __nv_bfloat16 g_oh[(size_t)NT * Dx],  g_ol[(size_t)NT * Dx];   // attn out
__device__ __nv_bfloat16 g_fh[(size_t)NT * FFx], g_fl[(size_t)NT * FFx];  // FFN mid

// transposed+split weights [N][K]: per layer q(16384) k v o w1(65536) w2(65536)
#define LW 196608
__device__ __nv_bfloat16 g_wh[(size_t)NLx * LW], g_wl[(size_t)NLx * LW];

// ---------------------------------------------------------------------------
// Baseline-PTX tensor core helpers (sm_80+; compiles at compute_103)
// ---------------------------------------------------------------------------
__device__ __forceinline__ uint32_t smem_u32(const void* p) {
    uint32_t a;
    asm("{ .reg .u64 t; cvta.to.shared.u64 t, %1; cvt.u32.u64 %0, t; }" : "=r"(a) : "l"(p));
    return a;
}
__device__ __forceinline__ void ldm4(uint32_t* r, uint32_t addr) {
    asm volatile("ldmatrix.sync.aligned.m8n8.x4.shared.b16 {%0,%1,%2,%3}, [%4];"
                 : "=r"(r[0]), "=r"(r[1]), "=r"(r[2]), "=r"(r[3]) : "r"(addr));
}
__device__ __forceinline__ void mma_bf16(float* d, const uint32_t* a, const uint32_t* b) {
    asm volatile("mma.sync.aligned.m16n8k16.row.col.f32.bf16.bf16.f32 "
                 "{%0,%1,%2,%3}, {%4,%5,%6,%7}, {%8,%9}, {%0,%1,%2,%3};"
                 : "+f"(d[0]), "+f"(d[1]), "+f"(d[2]), "+f"(d[3])
                 : "r"(a[0]), "r"(a[1]), "r"(a[2]), "r"(a[3]), "r"(b[0]), "r"(b[1]));
}
#define CP_COMMIT() asm volatile("cp.async.commit_group;" ::: "memory")
#define CP_WAIT0()  asm volatile("cp.async.wait_group 0;" ::: "memory")

// ---------------------------------------------------------------------------
// Weight transpose + bf16 split: T[n*K+k] = W[k*N+n] as hi/lo planes.
// ---------------------------------------------------------------------------
__global__ void wconv_k(const float* __restrict__ W,
                        __nv_bfloat16* __restrict__ Th,
                        __nv_bfloat16* __restrict__ Tl, int K, int N) {
    int idx = blockIdx.x * 256 + threadIdx.x;
    if (idx >= K * N) return;
    int n = idx / K, k = idx % K;
    float v = W[(size_t)k * N + n];
    __nv_bfloat16 h = __float2bfloat16(v);
    Th[idx] = h;
    Tl[idx] = __float2bfloat16(v - __bfloat162float(h));
}

// ---------------------------------------------------------------------------
// Embedding (fp32 residual stream)
// ---------------------------------------------------------------------------
__global__ void embed_k(const int* __restrict__ seqs, const float* __restrict__ tok,
                        const float* __restrict__ pos, float* __restrict__ x) {
    int t = blockIdx.x * 8 + (threadIdx.x >> 5);
    int lane = threadIdx.x & 31;
    if (t >= NT) return;
    int id = seqs[t], l = t % Lx;
    float4 te = *(const float4*)(tok + (size_t)id * Dx + lane * 4);
    float4 pe = *(const float4*)(pos + (size_t)l  * Dx + lane * 4);
    *(float4*)(x + (size_t)t * Dx + lane * 4) =
        make_float4(te.x + pe.x, te.y + pe.y, te.z + pe.z, te.w + pe.w);
}

// ---------------------------------------------------------------------------
// LayerNorm -> bf16 hi/lo planes
// ---------------------------------------------------------------------------
__global__ void ln_k(const float* __restrict__ x, const float* __restrict__ w,
                     const float* __restrict__ b,
                     __nv_bfloat16* __restrict__ oh, __nv_bfloat16* __restrict__ ol) {
    int r = blockIdx.x * 8 + (threadIdx.x >> 5);
    int lane = threadIdx.x & 31;
    if (r >= NT) return;
    float4 v = *(const float4*)(x + (size_t)r * Dx + lane * 4);
    float s = v.x + v.y + v.z + v.w;
#pragma unroll
    for (int o = 16; o; o >>= 1) s += __shfl_xor_sync(~0u, s, o);
    float mu = s * (1.f / 128.f);
    float dx = v.x - mu, dy = v.y - mu, dz = v.z - mu, dw = v.w - mu;
    float s2 = dx*dx + dy*dy + dz*dz + dw*dw;
#pragma unroll
    for (int o = 16; o; o >>= 1) s2 += __shfl_xor_sync(~0u, s2, o);
    float rs = rsqrtf(s2 * (1.f / 128.f) + 1e-5f);
    float4 wv = *(const float4*)(w + lane * 4);
    float4 bv = *(const float4*)(b + lane * 4);
    float y0 = dx*rs*wv.x + bv.x, y1 = dy*rs*wv.y + bv.y;
    float y2 = dz*rs*wv.z + bv.z, y3 = dw*rs*wv.w + bv.w;
    __nv_bfloat16 h0 = __float2bfloat16(y0), h1 = __float2bfloat16(y1);
    __nv_bfloat16 h2 = __float2bfloat16(y2), h3 = __float2bfloat16(y3);
    __nv_bfloat16 l0 = __float2bfloat16(y0 - __bfloat162float(h0));
    __nv_bfloat16 l1 = __float2bfloat16(y1 - __bfloat162float(h1));
    __nv_bfloat16 l2 = __float2bfloat16(y2 - __bfloat162float(h2));
    __nv_bfloat16 l3 = __float2bfloat16(y3 - __bfloat162float(h3));
    size_t o = (size_t)r * Dx + lane * 4;
    *(__nv_bfloat162*)(oh + o)     = __halves2bfloat162(h0, h1);
    *(__nv_bfloat162*)(oh + o + 2) = __halves2bfloat162(h2, h3);
    *(__nv_bfloat162*)(ol + o)     = __halves2bfloat162(l0, l1);
    *(__nv_bfloat162*)(ol + o + 2) = __halves2bfloat162(l2, l3);
}

// ---------------------------------------------------------------------------
// Pipelined tensor-core GEMM, 512 threads (16 warps, 32x32 warp tiles).
// EPI: 1=gelu(+bias)->bf16 planes; 2=+bias+res->fp32; 5=fused QKV
// ---------------------------------------------------------------------------
#define PAD 136
#define PLANE (128 * PAD * 2)       // 34816 bytes
#define TG_SMEM (6 * PLANE)         // 208896 bytes
#define W2_SMEM (4 * PLANE)         // 139264 bytes

__device__ __forceinline__ void stage_async(const __nv_bfloat16* __restrict__ src, int ld,
                                            uint32_t smbase, int tid) {
#pragma unroll
    for (int it = 0; it < 4; ++it) {
        int i = it * 512 + tid;
        int row = i >> 4, seg = (i & 15) << 3;
        uint32_t dst = smbase + (row * PAD + seg) * 2;
        asm volatile("cp.async.cg.shared.global [%0], [%1], 16;"
                     :: "r"(dst), "l"(src + (size_t)row * ld + seg) : "memory");
    }
}

// One K=128 chunk of 128x128 x (hi/lo split) MMA into acc[2][4][4].
__device__ __forceinline__ void mma_chunk(
    float acc[2][4][4], uint32_t sAh, uint32_t sAl, uint32_t sBh, uint32_t sBl,
    uint32_t aoff, uint32_t boff)
{
#pragma unroll
    for (int ks = 0; ks < 8; ++ks) {
        uint32_t kb = ks * 32;
        uint32_t fah[2][4], fal[2][4], fbh[4][2], fbl[4][2];
#pragma unroll
        for (int mi = 0; mi < 2; ++mi) {
            uint32_t ro = mi * 16 * PAD * 2 + kb;
            ldm4(fah[mi], sAh + aoff + ro);
            ldm4(fal[mi], sAl + aoff + ro);
        }
#pragma unroll
        for (int np = 0; np < 2; ++np) {
            uint32_t ro = np * 16 * PAD * 2 + kb;
            ldm4(&fbh[2 * np][0], sBh + boff + ro);
            ldm4(&fbl[2 * np][0], sBl + boff + ro);
        }
#pragma unroll
        for (int mi = 0; mi < 2; ++mi)
#pragma unroll
            for (int ni = 0; ni < 4; ++ni) {
                mma_bf16(acc[mi][ni], fah[mi], fbh[ni]);
                mma_bf16(acc[mi][ni], fah[mi], fbl[ni]);
                mma_bf16(acc[mi][ni], fal[mi], fbh[ni]);
            }
    }
}

template <int EPI>
__global__ void __launch_bounds__(512) tgemm(
    const __nv_bfloat16* __restrict__ Ah, const __nv_bfloat16* __restrict__ Al, int lda,
    const __nv_bfloat16* __restrict__ Bh, const __nv_bfloat16* __restrict__ Bl,
    const float* __restrict__ bias, const float* __restrict__ bias2,
    const float* __restrict__ bias3, const float* __restrict__ res,
    float* __restrict__ Cf, float* __restrict__ Cf2, float* __restrict__ Cf3,
    __nv_bfloat16* __restrict__ Chh, __nv_bfloat16* __restrict__ Chl,
    int ldc, int mTiles)
{
    extern __shared__ char smraw[];
    uint32_t sb = smem_u32(smraw);
    const uint32_t sBh = sb, sBl = sb + PLANE;

    int tid = threadIdx.x, wid = tid >> 5, lane = tid & 31;
    int wm = wid >> 2, wn = wid & 3;      // 32x32 warp tile
    int n0;
    if (EPI == 5) {
        n0 = 0;
        int sel = blockIdx.x;
        Bh  += sel * 16384;  Bl += sel * 16384;
        bias = (sel == 0) ? bias : (sel == 1) ? bias2 : bias3;
        Cf   = (sel == 0) ? Cf   : (sel == 1) ? Cf2   : Cf3;
    } else {
        n0 = blockIdx.x * 128;
    }
    int mt0 = blockIdx.y;

    stage_async(Bh + (size_t)n0 * lda, lda, sBh, tid);
    stage_async(Bl + (size_t)n0 * lda, lda, sBl, tid);
    if (mt0 < mTiles) {
        stage_async(Ah + (size_t)(mt0 * 128) * lda, lda, sb + 2 * PLANE, tid);
        stage_async(Al + (size_t)(mt0 * 128) * lda, lda, sb + 3 * PLANE, tid);
    }
    CP_COMMIT();
    CP_WAIT0();
    __syncthreads();

    const uint32_t aoff = ((wm * 32 + (lane & 15)) * PAD + (lane >> 4) * 8) * 2;
    const uint32_t boff = ((wn * 32 + ((lane >> 4) << 3) + (lane & 7)) * PAD
                          + ((lane >> 3) & 1) * 8) * 2;

    int buf = 0;
    for (int mt = mt0; mt < mTiles; mt += gridDim.y) {
        int m0 = mt * 128;
        int next = mt + gridDim.y;
        if (next < mTiles) {
            uint32_t nb = sb + (2 + 2 * (buf ^ 1)) * PLANE;
            stage_async(Ah + (size_t)(next * 128) * lda, lda, nb, tid);
            stage_async(Al + (size_t)(next * 128) * lda, lda, nb + PLANE, tid);
            CP_COMMIT();
        }
        const uint32_t sAh = sb + (2 + 2 * buf) * PLANE, sAl = sAh + PLANE;

        float acc[2][4][4];
#pragma unroll
        for (int mi = 0; mi < 2; ++mi)
#pragma unroll
            for (int ni = 0; ni < 4; ++ni)
#pragma unroll
                for (int e = 0; e < 4; ++e) acc[mi][ni][e] = 0.f;

        mma_chunk(acc, sAh, sAl, sBh, sBl, aoff, boff);

        int gp = lane >> 2, t4 = lane & 3;
#pragma unroll
        for (int mi = 0; mi < 2; ++mi) {
            int mrow = m0 + wm * 32 + mi * 16 + gp;
#pragma unroll
            for (int ni = 0; ni < 4; ++ni) {
                int ncol = n0 + wn * 32 + ni * 8 + t4 * 2;
                float d0 = acc[mi][ni][0], d1 = acc[mi][ni][1];
                float d2 = acc[mi][ni][2], d3 = acc[mi][ni][3];
                float b0 = bias[ncol], b1 = bias[ncol + 1];
                d0 += b0; d1 += b1; d2 += b0; d3 += b1;
                size_t ci0 = (size_t)mrow * ldc + ncol;
                size_t ci1 = (size_t)(mrow + 8) * ldc + ncol;
                if (EPI == 1) {
                    d0 = 0.5f * d0 * (1.f + erff(d0 * 0.7071067811865476f));
                    d1 = 0.5f * d1 * (1.f + erff(d1 * 0.7071067811865476f));
                    d2 = 0.5f * d2 * (1.f + erff(d2 * 0.7071067811865476f));
                    d3 = 0.5f * d3 * (1.f + erff(d3 * 0.7071067811865476f));
                    __nv_bfloat16 h0 = __float2bfloat16(d0), h1 = __float2bfloat16(d1);
                    __nv_bfloat16 h2 = __float2bfloat16(d2), h3 = __float2bfloat16(d3);
                    *(__nv_bfloat162*)(Chh + ci0) = __halves2bfloat162(h0, h1);
                    *(__nv_bfloat162*)(Chh + ci1) = __halves2bfloat162(h2, h3);
                    *(__nv_bfloat162*)(Chl + ci0) = __halves2bfloat162(
                        __float2bfloat16(d0 - __bfloat162float(h0)),
                        __float2bfloat16(d1 - __bfloat162float(h1)));
                    *(__nv_bfloat162*)(Chl + ci1) = __halves2bfloat162(
                        __float2bfloat16(d2 - __bfloat162float(h2)),
                        __float2bfloat16(d3 - __bfloat162float(h3)));
                } else {
                    if (EPI == 2) {
                        float2 r0 = *(const float2*)(res + ci0);
                        float2 r1 = *(const float2*)(res + ci1);
                        d0 += r0.x; d1 += r0.y; d2 += r1.x; d3 += r1.y;
                    }
                    *(float2*)(Cf + ci0) = make_float2(d0, d1);
                    *(float2*)(Cf + ci1) = make_float2(d2, d3);
                }
            }
        }
        if (next < mTiles) CP_WAIT0();
        __syncthreads();
        buf ^= 1;
    }
}

// ---------------------------------------------------------------------------
// W2 GEMM (K=512): in-kernel 4-chunk loop. out = acc + bias + res.
// ---------------------------------------------------------------------------
__global__ void __launch_bounds__(512) tgemm_w2(
    const __nv_bfloat16* __restrict__ Ah, const __nv_bfloat16* __restrict__ Al,
    const __nv_bfloat16* __restrict__ Bh, const __nv_bfloat16* __restrict__ Bl,
    const float* __restrict__ bias, const float* __restrict__ res,
    float* __restrict__ Cf, int mTiles)
{
    extern __shared__ char smraw[];
    uint32_t sb = smem_u32(smraw);
    const uint32_t sAh = sb, sAl = sb + PLANE, sBh = sb + 2 * PLANE, sBl = sb + 3 * PLANE;
    const int lda = FFx, ldc = Dx;

    int tid = threadIdx.x, wid = tid >> 5, lane = tid & 31;
    int wm = wid >> 2, wn = wid & 3;

    const uint32_t aoff = ((wm * 32 + (lane & 15)) * PAD + (lane >> 4) * 8) * 2;
    const uint32_t boff = ((wn * 32 + ((lane >> 4) << 3) + (lane & 7)) * PAD
                          + ((lane >> 3) & 1) * 8) * 2;

    for (int mt = blockIdx.y; mt < mTiles; mt += gridDim.y) {
        int m0 = mt * 128;
        float acc[2][4][4];
#pragma unroll
        for (int mi = 0; mi < 2; ++mi)
#pragma unroll
            for (int ni = 0; ni < 4; ++ni)
#pragma unroll
                for (int e = 0; e < 4; ++e) acc[mi][ni][e] = 0.f;

        for (int c = 0; c < 4; ++c) {
            __syncthreads();
            stage_async(Bh + c * 128, lda, sBh, tid);
            stage_async(Bl + c * 128, lda, sBl, tid);
            stage_async(Ah + (size_t)m0 * lda + c * 128, lda, sAh, tid);
            stage_async(Al + (size_t)m0 * lda + c * 128, lda, sAl, tid);
            CP_COMMIT();
            CP_WAIT0();
            __syncthreads();

            mma_chunk(acc, sAh, sAl, sBh, sBl, aoff, boff);
        }

        int gp = lane >> 2, t4 = lane & 3;
#pragma unroll
        for (int mi = 0; mi < 2; ++mi) {
            int mrow = m0 + wm * 32 + mi * 16 + gp;
#pragma unroll
            for (int ni = 0; ni < 4; ++ni) {
                int ncol = wn * 32 + ni * 8 + t4 * 2;
                float d0 = acc[mi][ni][0], d1 = acc[mi][ni][1];
                float d2 = acc[mi][ni][2], d3 = acc[mi][ni][3];
                float b0 = bias[ncol], b1 = bias[ncol + 1];
                size_t ci0 = (size_t)mrow * ldc + ncol;
                size_t ci1 = (size_t)(mrow + 8) * ldc + ncol;
                float2 r0 = *(const float2*)(res + ci0);
                float2 r1 = *(const float2*)(res + ci1);
                *(float2*)(Cf + ci0) = make_float2(d0 + b0 + r0.x, d1 + b1 + r0.y);
                *(float2*)(Cf + ci1) = make_float2(d2 + b0 + r1.x, d3 + b1 + r1.y);
            }
        }
        __syncthreads();
    }
}

// ---------------------------------------------------------------------------
// Fused masked attention, 2 queries/warp pass, vectorized smem access.
// ---------------------------------------------------------------------------
#define AKS 36
#define AVS 204
#define ATTN_SMEM_FLOATS (200*AKS + 32*AVS + 200 + 8*2*AVS)
#define ATTN_SMEM_BYTES  (ATTN_SMEM_FLOATS * 4)

__global__ void __launch_bounds__(256) attn_k(
    const float* __restrict__ Q, const float* __restrict__ Kx,
    const float* __restrict__ Vx, const int* __restrict__ seqs,
    __nv_bfloat16* __restrict__ Oh, __nv_bfloat16* __restrict__ Ol)
{
    int h = blockIdx.x, b = blockIdx.y;
    extern __shared__ float sm[];
    float* Ks   = sm;                    // [200][36]
    float* Vt   = Ks + 200 * AKS;        // [32][204] transposed
    float* flag = Vt + 32 * AVS;         // [200]
    float* ps   = flag + 200;            // [8 warps][2 queries][204]

    int tid = threadIdx.x;
    size_t base = ((size_t)b * Lx) * Dx + h * DKx;

    for (int idx = tid; idx < 1600; idx += 256) {
        int l = idx >> 3, i = idx & 7;
        float4 v = *(const float4*)(Kx + base + (size_t)l * Dx + i * 4);
        *(float4*)(Ks + l * AKS + i * 4) = v;
    }
    for (int idx = tid; idx < 6400; idx += 256) {
        int l = idx >> 5, d = idx & 31;
        Vt[d * AVS + l] = Vx[base + (size_t)l * Dx + d];
    }
    for (int l = tid; l < 200; l += 256)
        flag[l] = (seqs[b * Lx + l] > 0) ? 1.f : 0.f;
    __syncthreads();

    int warp = tid >> 5, lane = tid & 31;
    float* psw = ps + warp * 2 * AVS;
    const float scale = 0.17677669529663687f;

    for (int qp = warp; qp < 100; qp += 8) {
        int q0 = qp, q1 = qp + 100;
        float4 qa[8], qb[8];
        const float4* q0p = (const float4*)(Q + base + (size_t)q0 * Dx);
        const float4* q1p = (const float4*)(Q + base + (size_t)q1 * Dx);
#pragma unroll
        for (int i = 0; i < 8; ++i) { qa[i] = q0p[i]; qb[i] = q1p[i]; }

        float s0[7], s1[7], mx0 = -1e30f, mx1 = -1e30f;
#pragma unroll
        for (int j = 0; j < 7; ++j) {
            int k = j * 32 + lane;
            const float* kr = Ks + k * AKS;
            float d0 = 0.f, d1 = 0.f;
#pragma unroll
            for (int i = 0; i < 8; ++i) {
                float4 kv = *(const float4*)(kr + i * 4);
                d0 = fmaf(qa[i].x, kv.x, d0); d0 = fmaf(qa[i].y, kv.y, d0);
                d0 = fmaf(qa[i].z, kv.z, d0); d0 = fmaf(qa[i].w, kv.w, d0);
                d1 = fmaf(qb[i].x, kv.x, d1); d1 = fmaf(qb[i].y, kv.y, d1);
                d1 = fmaf(qb[i].z, kv.z, d1); d1 = fmaf(qb[i].w, kv.w, d1);
            }
            bool valid = (k < 200);
            float fl = valid ? flag[k] : 0.f;
            float v0 = (fl != 0.f) ? d0 * scale : -1e9f;
            float v1 = (fl != 0.f) ? d1 * scale : -1e9f;
            s0[j] = valid ? v0 : -1e30f;
            s1[j] = valid ? v1 : -1e30f;
            mx0 = fmaxf(mx0, s0[j]);
            mx1 = fmaxf(mx1, s1[j]);
        }
#pragma unroll
        for (int o = 16; o; o >>= 1) {
            mx0 = fmaxf(mx0, __shfl_xor_sync(~0u, mx0, o));
            mx1 = fmaxf(mx1, __shfl_xor_sync(~0u, mx1, o));
        }

        float p0[7], p1[7], sum0 = 0.f, sum1 = 0.f;
#pragma unroll
        for (int j = 0; j < 7; ++j) {
            p0[j] = expf(s0[j] - mx0); sum0 += p0[j];
            p1[j] = expf(s1[j] - mx1); sum1 += p1[j];
        }
#pragma unroll
        for (int o = 16; o; o >>= 1) {
            sum0 += __shfl_xor_sync(~0u, sum0, o);
            sum1 += __shfl_xor_sync(~0u, sum1, o);
        }
        float inv0 = 1.f / sum0, inv1 = 1.f / sum1;

#pragma unroll
        for (int j = 0; j < 7; ++j) {
            int k = j * 32 + lane;
            if (k < 200) { psw[k] = p0[j]; psw[AVS + k] = p1[j]; }
        }
        __syncwarp();

        float a0 = 0.f, a1 = 0.f;
        const float* vr = Vt + lane * AVS;
#pragma unroll
        for (int kg = 0; kg < 50; ++kg) {
            float4 pv0 = *(const float4*)(psw + kg * 4);
            float4 pv1 = *(const float4*)(psw + AVS + kg * 4);
            float4 vv  = *(const float4*)(vr + kg * 4);
            a0 = fmaf(pv0.x, vv.x, a0); a0 = fmaf(pv0.y, vv.y, a0);
            a0 = fmaf(pv0.z, vv.z, a0); a0 = fmaf(pv0.w, vv.w, a0);
            a1 = fmaf(pv1.x, vv.x, a1); a1 = fmaf(pv1.y, vv.y, a1);
            a1 = fmaf(pv1.z, vv.z, a1); a1 = fmaf(pv1.w, vv.w, a1);
        }
        float vo0 = a0 * inv0, vo1 = a1 * inv1;
        __nv_bfloat16 h0 = __float2bfloat16(vo0), h1 = __float2bfloat16(vo1);
        Oh[base + (size_t)q0 * Dx + lane] = h0;
        Ol[base + (size_t)q0 * Dx + lane] = __float2bfloat16(vo0 - __bfloat162float(h0));
        Oh[base + (size_t)q1 * Dx + lane] = h1;
        Ol[base + (size_t)q1 * Dx + lane] = __float2bfloat16(vo1 - __bfloat162float(h1));
        __syncwarp();
    }
}

// ---------------------------------------------------------------------------
// fp32 SGEMM (final FC split-K, raw partials)
// ---------------------------------------------------------------------------
__global__ void __launch_bounds__(256) gemm_fc(
    const float* __restrict__ A, int lda,
    const float* __restrict__ B, int ldb,
    float* __restrict__ C, int ldc, int M, int kChunk)
{
    __shared__ float As[16][128];
    __shared__ float Bs[16][128];
    const int tid = threadIdx.x;
    const int m0 = blockIdx.y * 128, n0 = blockIdx.x * 128;
    const int kStart = blockIdx.z * kChunk;
    const float* Ap = A + (size_t)m0 * lda + kStart;
    const float* Bp = B + (size_t)kStart * ldb + n0;
    const int tx = tid & 15, ty = tid >> 4;
    const int arow = tid >> 2, acol = (tid & 3) << 2;
    const int brow = tid >> 5, bcol = (tid & 31) << 2;

    float acc[8][8];
#pragma unroll
    for (int i = 0; i < 8; ++i)
#pragma unroll
        for (int j = 0; j < 8; ++j) acc[i][j] = 0.f;

    for (int kt = 0; kt < kChunk; kt += 16) {
        float4 a0 = *(const float4*)(Ap + (size_t)arow        * lda + kt + acol);
        float4 a1 = *(const float4*)(Ap + (size_t)(arow + 64) * lda + kt + acol);
        float4 b0 = *(const float4*)(Bp + (size_t)(kt + brow)     * ldb + bcol);
        float4 b1 = *(const float4*)(Bp + (size_t)(kt + brow + 8) * ldb + bcol);
        __syncthreads();
        As[acol + 0][arow] = a0.x; As[acol + 1][arow] = a0.y;
        As[acol + 2][arow] = a0.z; As[acol + 3][arow] = a0.w;
        As[acol + 0][arow + 64] = a1.x; As[acol + 1][arow + 64] = a1.y;
        As[acol + 2][arow + 64] = a1.z; As[acol + 3][arow + 64] = a1.w;
        *(float4*)&Bs[brow][bcol] = b0;
        *(float4*)&Bs[brow + 8][bcol] = b1;
        __syncthreads();
#pragma unroll
        for (int kk = 0; kk < 16; ++kk) {
            float a[8], bb[8];
            *(float4*)(a)      = *(const float4*)&As[kk][ty * 8];
            *(float4*)(a + 4)  = *(const float4*)&As[kk][ty * 8 + 4];
            *(float4*)(bb)     = *(const float4*)&Bs[kk][tx * 8];
            *(float4*)(bb + 4) = *(const float4*)&Bs[kk][tx * 8 + 4];
#pragma unroll
            for (int i = 0; i < 8; ++i)
#pragma unroll
                for (int j = 0; j < 8; ++j)
                    acc[i][j] = fmaf(a[i], bb[j], acc[i][j]);
        }
    }

    float* Cp = C + (size_t)blockIdx.z * M * ldc;
#pragma unroll
    for (int i = 0; i < 8; ++i) {
        int m = m0 + ty * 8 + i;
#pragma unroll
        for (int j = 0; j < 8; j += 4) {
            int n = n0 + tx * 8 + j;
            *(float4*)(Cp + (size_t)m * ldc + n) =
                make_float4(acc[i][j], acc[i][j+1], acc[i][j+2], acc[i][j+3]);
        }
    }
}

__global__ void fcred_k(const float* __restrict__ part, const float* __restrict__ bias,
                        float* __restrict__ out) {
    int idx = blockIdx.x * 256 + threadIdx.x;
    if (idx >= Bx * Dx) return;
    float s = 0.f;
#pragma unroll
    for (int z = 0; z < FC_SPLIT; ++z) s += part[(size_t)z * Bx * Dx + idx];
    out[idx] = s + bias[idx & (Dx - 1)];
}

// ---------------------------------------------------------------------------
// Host driver (graph-capturable: kernel launches only)
// ---------------------------------------------------------------------------
extern "C" void kernel_launch(void* const* d_in, const int* in_sizes, int n_in,
                              void* d_out, int out_size) {
    (void)in_sizes; (void)n_in; (void)out_size;
    const int*   seqs = (const int*)  d_in[0];
    const float* tok  = (const float*)d_in[1];
    const float* pos  = (const float*)d_in[2];
    const float* Wq   = (const float*)d_in[3];
    const float* bq   = (const float*)d_in[4];
    const float* Wk   = (const float*)d_in[5];
    const float* bk   = (const float*)d_in[6];
    const float* Wv   = (const float*)d_in[7];
    const float* bv   = (const float*)d_in[8];
    const float* Wo   = (const float*)d_in[9];
    const float* bo   = (const float*)d_in[10];
    const float* ln1w = (const float*)d_in[11];
    const float* ln1b = (const float*)d_in[12];
    const float* ln2w = (const float*)d_in[13];
    const float* ln2b = (const float*)d_in[14];
    const float* W1   = (const float*)d_in[15];
    const float* b1   = (const float*)d_in[16];
    const float* W2   = (const float*)d_in[17];
    const float* b2   = (const float*)d_in[18];
    const float* fcW  = (const float*)d_in[19];
    const float* fcb  = (const float*)d_in[20];
    float* out = (float*)d_out;

    float *px, *pq, *pk, *pv, *pp;
    __nv_bfloat16 *ah, *al, *oh, *ol, *fh, *fl, *wh, *wl;
    cudaGetSymbolAddress((void**)&px, g_x);
    cudaGetSymbolAddress((void**)&pq, g_q);
    cudaGetSymbolAddress((void**)&pk, g_k);
    cudaGetSymbolAddress((void**)&pv, g_v);
    cudaGetSymbolAddress((void**)&pp, g_fcp);
    cudaGetSymbolAddress((void**)&ah, g_ah);
    cudaGetSymbolAddress((void**)&al, g_al);
    cudaGetSymbolAddress((void**)&oh, g_oh);
    cudaGetSymbolAddress((void**)&ol, g_ol);
    cudaGetSymbolAddress((void**)&fh, g_fh);
    cudaGetSymbolAddress((void**)&fl, g_fl);
    cudaGetSymbolAddress((void**)&wh, g_wh);
    cudaGetSymbolAddress((void**)&wl, g_wl);

    cudaFuncSetAttribute(attn_k, cudaFuncAttributeMaxDynamicSharedMemorySize, ATTN_SMEM_BYTES);
    cudaFuncSetAttribute(tgemm<1>, cudaFuncAttributeMaxDynamicSharedMemorySize, TG_SMEM);
    cudaFuncSetAttribute(tgemm<2>, cudaFuncAttributeMaxDynamicSharedMemorySize, TG_SMEM);
    cudaFuncSetAttribute(tgemm<5>, cudaFuncAttributeMaxDynamicSharedMemorySize, TG_SMEM);
    cudaFuncSetAttribute(tgemm_w2, cudaFuncAttributeMaxDynamicSharedMemorySize, W2_SMEM);

    // --- weight transpose + split (tiny) ---
    for (int l = 0; l < NLx; ++l) {
        size_t wb = (size_t)l * LW;
        wconv_k<<<64,  256>>>(Wq + (size_t)l*Dx*Dx,   wh + wb,          wl + wb,          Dx,  Dx);
        wconv_k<<<64,  256>>>(Wk + (size_t)l*Dx*Dx,   wh + wb + 16384,  wl + wb + 16384,  Dx,  Dx);
        wconv_k<<<64,  256>>>(Wv + (size_t)l*Dx*Dx,   wh + wb + 32768,  wl + wb + 32768,  Dx,  Dx);
        wconv_k<<<64,  256>>>(Wo + (size_t)l*Dx*Dx,   wh + wb + 49152,  wl + wb + 49152,  Dx,  Dx);
        wconv_k<<<256, 256>>>(W1 + (size_t)l*Dx*FFx,  wh + wb + 65536,  wl + wb + 65536,  Dx,  FFx);
        wconv_k<<<256, 256>>>(W2 + (size_t)l*FFx*Dx,  wh + wb + 131072, wl + wb + 131072, FFx, Dx);
    }

    const dim3 gRow(NT / 8);
    const int  MT = NT / 128;  // 1600

    embed_k<<<gRow, 256>>>(seqs, tok, pos, px);

    for (int i = 0; i < NLx; ++i) {
        size_t wb = (size_t)i * LW;
        // --- attention block ---
        ln_k<<<gRow, 256>>>(px, ln1w + i * Dx, ln1b + i * Dx, ah, al);
        tgemm<5><<<dim3(3,148), 512, TG_SMEM>>>(ah, al, Dx, wh + wb, wl + wb,
                 bq + i*Dx, bk + i*Dx, bv + i*Dx, nullptr,
                 pq, pk, pv, nullptr, nullptr, Dx, MT);
        attn_k<<<dim3(Hx, Bx), 256, ATTN_SMEM_BYTES>>>(pq, pk, pv, seqs, oh, ol);
        tgemm<2><<<dim3(1,148), 512, TG_SMEM>>>(oh, ol, Dx, wh + wb + 49152, wl + wb + 49152,
                 bo + i*Dx, nullptr, nullptr, px,
                 px, nullptr, nullptr, nullptr, nullptr, Dx, MT);
        // --- FFN block ---
        ln_k<<<gRow, 256>>>(px, ln2w + i * Dx, ln2b + i * Dx, ah, al);
        tgemm<1><<<dim3(4,37), 512, TG_SMEM>>>(ah, al, Dx, wh + wb + 65536, wl + wb + 65536,
                 b1 + i*FFx, nullptr, nullptr, nullptr,
                 nullptr, nullptr, nullptr, fh, fl, FFx, MT);
        tgemm_w2<<<dim3(1,148), 512, W2_SMEM>>>(fh, fl, wh + wb + 131072, wl + wb + 131072,
                 b2 + i*Dx, px, px, MT);
    }

    // Final FC (fp32 split-K, deterministic reduce)
    gemm_fc<<<dim3(1, Bx / 128, FC_SPLIT), 256>>>(
        px, Lx * Dx, fcW, Dx, pp, Dx, Bx, (Lx * Dx) / FC_SPLIT);
    fcred_k<<<(Bx * Dx + 255) / 256, 256>>>(pp, fcb, out);
}

// round 13
// speedup vs baseline: 1.0170x; 1.0170x over previous
#include <cuda_runtime.h>
#include <cuda_bf16.h>
#include <math.h>
#include <stdint.h>

// Problem constants
#define Bx   1024
#define Lx   200
#define Dx   128
#define Hx   4
#define DKx  32
#define FFx  512
#define NLx  2
#define NT   (Bx*Lx)          // 204800 tokens
#define FC_SPLIT 32

// ---------------------------------------------------------------------------
// Device-global scratch (allocation-free rule).
// ---------------------------------------------------------------------------
__device__ float g_x  [(size_t)NT * Dx];    // residual stream (fp32)
__device__ float g_q  [(size_t)NT * Dx];
__device__ float g_k  [(size_t)NT * Dx];
__device__ float g_v  [(size_t)NT * Dx];
__device__ float g_fcp[(size_t)FC_SPLIT * Bx * Dx];

// bf16 hi/lo activation planes
__device__ __nv_bfloat16 g_ah[(size_t)NT * Dx],  g_al[(size_t)NT * Dx];   // LN out
__device__ __nv_bfloat16 g_oh[(size_t)NT * Dx],  g_ol[(size_t)NT * Dx];   // attn out
__device__ __nv_bfloat16 g_fh[(size_t)NT * FFx], g_fl[(size_t)NT * FFx];  // FFN mid

// transposed+split weights [N][K]: per layer q(16384) k v o w1(65536) w2(65536)
#define LW 196608
__device__ __nv_bfloat16 g_wh[(size_t)NLx * LW], g_wl[(size_t)NLx * LW];

// ---------------------------------------------------------------------------
// Baseline-PTX tensor core helpers (sm_80+; compiles at compute_103)
// ---------------------------------------------------------------------------
__device__ __forceinline__ uint32_t smem_u32(const void* p) {
    uint32_t a;
    asm("{ .reg .u64 t; cvta.to.shared.u64 t, %1; cvt.u32.u64 %0, t; }" : "=r"(a) : "l"(p));
    return a;
}
__device__ __forceinline__ void ldm4(uint32_t* r, uint32_t addr) {
    asm volatile("ldmatrix.sync.aligned.m8n8.x4.shared.b16 {%0,%1,%2,%3}, [%4];"
                 : "=r"(r[0]), "=r"(r[1]), "=r"(r[2]), "=r"(r[3]) : "r"(addr));
}
__device__ __forceinline__ void mma_bf16(float* d, const uint32_t* a, const uint32_t* b) {
    asm volatile("mma.sync.aligned.m16n8k16.row.col.f32.bf16.bf16.f32 "
                 "{%0,%1,%2,%3}, {%4,%5,%6,%7}, {%8,%9}, {%0,%1,%2,%3};"
                 : "+f"(d[0]), "+f"(d[1]), "+f"(d[2]), "+f"(d[3])
                 : "r"(a[0]), "r"(a[1]), "r"(a[2]), "r"(a[3]), "r"(b[0]), "r"(b[1]));
}
#define CP_COMMIT() asm volatile("cp.async.commit_group;" ::: "memory")
#define CP_WAIT0()  asm volatile("cp.async.wait_group 0;" ::: "memory")

// ---------------------------------------------------------------------------
// Single-launch weight transpose + bf16 split for ALL layers/weights.
// Layout per layer in g_wh/g_wl: q(16384) k(16384) v(16384) o(16384)
//                                w1(65536, K=128,N=512) w2(65536, K=512,N=128)
// ---------------------------------------------------------------------------
__global__ void wconv_all(const float* __restrict__ Wq, const float* __restrict__ Wk,
                          const float* __restrict__ Wv, const float* __restrict__ Wo,
                          const float* __restrict__ W1, const float* __restrict__ W2,
                          __nv_bfloat16* __restrict__ Th, __nv_bfloat16* __restrict__ Tl) {
    int idx = blockIdx.x * 256 + threadIdx.x;
    if (idx >= NLx * LW) return;
    int l = idx / LW, o = idx % LW;
    float v;
    if (o < 65536) {                      // q,k,v,o blocks (K=128,N=128)
        int seg = o >> 14, loc = o & 16383;
        int n = loc >> 7, k = loc & 127;
        const float* W = (seg == 0) ? Wq : (seg == 1) ? Wk : (seg == 2) ? Wv : Wo;
        v = W[(size_t)l * Dx * Dx + k * Dx + n];
    } else if (o < 131072) {              // w1: K=128, N=512
        int loc = o - 65536;
        int n = loc >> 7, k = loc & 127;
        v = W1[(size_t)l * Dx * FFx + k * FFx + n];
    } else {                              // w2: K=512, N=128
        int loc = o - 131072;
        int n = loc >> 9, k = loc & 511;
        v = W2[(size_t)l * FFx * Dx + k * Dx + n];
    }
    __nv_bfloat16 h = __float2bfloat16(v);
    Th[idx] = h;
    Tl[idx] = __float2bfloat16(v - __bfloat162float(h));
}

// ---------------------------------------------------------------------------
// Embedding (fp32 residual stream)
// ---------------------------------------------------------------------------
__global__ void embed_k(const int* __restrict__ seqs, const float* __restrict__ tok,
                        const float* __restrict__ pos, float* __restrict__ x) {
    int t = blockIdx.x * 8 + (threadIdx.x >> 5);
    int lane = threadIdx.x & 31;
    if (t >= NT) return;
    int id = seqs[t], l = t % Lx;
    float4 te = *(const float4*)(tok + (size_t)id * Dx + lane * 4);
    float4 pe = *(const float4*)(pos + (size_t)l  * Dx + lane * 4);
    *(float4*)(x + (size_t)t * Dx + lane * 4) =
        make_float4(te.x + pe.x, te.y + pe.y, te.z + pe.z, te.w + pe.w);
}

// ---------------------------------------------------------------------------
// LayerNorm -> bf16 hi/lo planes
// ---------------------------------------------------------------------------
__global__ void ln_k(const float* __restrict__ x, const float* __restrict__ w,
                     const float* __restrict__ b,
                     __nv_bfloat16* __restrict__ oh, __nv_bfloat16* __restrict__ ol) {
    int r = blockIdx.x * 8 + (threadIdx.x >> 5);
    int lane = threadIdx.x & 31;
    if (r >= NT) return;
    float4 v = *(const float4*)(x + (size_t)r * Dx + lane * 4);
    float s = v.x + v.y + v.z + v.w;
#pragma unroll
    for (int o = 16; o; o >>= 1) s += __shfl_xor_sync(~0u, s, o);
    float mu = s * (1.f / 128.f);
    float dx = v.x - mu, dy = v.y - mu, dz = v.z - mu, dw = v.w - mu;
    float s2 = dx*dx + dy*dy + dz*dz + dw*dw;
#pragma unroll
    for (int o = 16; o; o >>= 1) s2 += __shfl_xor_sync(~0u, s2, o);
    float rs = rsqrtf(s2 * (1.f / 128.f) + 1e-5f);
    float4 wv = *(const float4*)(w + lane * 4);
    float4 bv = *(const float4*)(b + lane * 4);
    float y0 = dx*rs*wv.x + bv.x, y1 = dy*rs*wv.y + bv.y;
    float y2 = dz*rs*wv.z + bv.z, y3 = dw*rs*wv.w + bv.w;
    __nv_bfloat16 h0 = __float2bfloat16(y0), h1 = __float2bfloat16(y1);
    __nv_bfloat16 h2 = __float2bfloat16(y2), h3 = __float2bfloat16(y3);
    __nv_bfloat16 l0 = __float2bfloat16(y0 - __bfloat162float(h0));
    __nv_bfloat16 l1 = __float2bfloat16(y1 - __bfloat162float(h1));
    __nv_bfloat16 l2 = __float2bfloat16(y2 - __bfloat162float(h2));
    __nv_bfloat16 l3 = __float2bfloat16(y3 - __bfloat162float(h3));
    size_t o = (size_t)r * Dx + lane * 4;
    *(__nv_bfloat162*)(oh + o)     = __halves2bfloat162(h0, h1);
    *(__nv_bfloat162*)(oh + o + 2) = __halves2bfloat162(h2, h3);
    *(__nv_bfloat162*)(ol + o)     = __halves2bfloat162(l0, l1);
    *(__nv_bfloat162*)(ol + o + 2) = __halves2bfloat162(l2, l3);
}

// ---------------------------------------------------------------------------
// Pipelined tensor-core GEMM, 256 threads (8 warps, 64x32 warp tiles),
// A double-buffered cp.async, B resident. B fragments via ldm4 (R12-validated
// lane mapping). EPI: 1=gelu(+bias)->bf16; 2=+bias+res->fp32; 5=fused QKV.
// ---------------------------------------------------------------------------
#define PAD 136
#define PLANE (128 * PAD * 2)       // 34816 bytes
#define TG_SMEM (6 * PLANE)         // 208896 bytes
#define W2_SMEM (4 * PLANE)         // 139264 bytes

__device__ __forceinline__ void stage_async(const __nv_bfloat16* __restrict__ src, int ld,
                                            uint32_t smbase, int tid) {
#pragma unroll
    for (int it = 0; it < 8; ++it) {
        int i = it * 256 + tid;
        int row = i >> 4, seg = (i & 15) << 3;
        uint32_t dst = smbase + (row * PAD + seg) * 2;
        asm volatile("cp.async.cg.shared.global [%0], [%1], 16;"
                     :: "r"(dst), "l"(src + (size_t)row * ld + seg) : "memory");
    }
}

// One K=128 chunk of 128x128 hi/lo-split MMA into acc[4][4][4]. 64x32 warp tile.
__device__ __forceinline__ void mma_chunk(
    float acc[4][4][4], uint32_t sAh, uint32_t sAl, uint32_t sBh, uint32_t sBl,
    uint32_t aoff, uint32_t boff)
{
#pragma unroll
    for (int ks = 0; ks < 8; ++ks) {
        uint32_t kb = ks * 32;
        uint32_t fah[4][4], fal[4][4], fbh[4][2], fbl[4][2];
#pragma unroll
        for (int mi = 0; mi < 4; ++mi) {
            uint32_t ro = mi * 16 * PAD * 2 + kb;
            ldm4(fah[mi], sAh + aoff + ro);
            ldm4(fal[mi], sAl + aoff + ro);
        }
#pragma unroll
        for (int np = 0; np < 2; ++np) {
            uint32_t ro = np * 16 * PAD * 2 + kb;
            ldm4(&fbh[2 * np][0], sBh + boff + ro);
            ldm4(&fbl[2 * np][0], sBl + boff + ro);
        }
#pragma unroll
        for (int mi = 0; mi < 4; ++mi)
#pragma unroll
            for (int ni = 0; ni < 4; ++ni) {
                mma_bf16(acc[mi][ni], fah[mi], fbh[ni]);
                mma_bf16(acc[mi][ni], fah[mi], fbl[ni]);
                mma_bf16(acc[mi][ni], fal[mi], fbh[ni]);
            }
    }
}

template <int EPI>
__global__ void __launch_bounds__(256) tgemm(
    const __nv_bfloat16* __restrict__ Ah, const __nv_bfloat16* __restrict__ Al, int lda,
    const __nv_bfloat16* __restrict__ Bh, const __nv_bfloat16* __restrict__ Bl,
    const float* __restrict__ bias, const float* __restrict__ bias2,
    const float* __restrict__ bias3, const float* __restrict__ res,
    float* __restrict__ Cf, float* __restrict__ Cf2, float* __restrict__ Cf3,
    __nv_bfloat16* __restrict__ Chh, __nv_bfloat16* __restrict__ Chl,
    int ldc, int mTiles)
{
    extern __shared__ char smraw[];
    uint32_t sb = smem_u32(smraw);
    const uint32_t sBh = sb, sBl = sb + PLANE;

    int tid = threadIdx.x, wid = tid >> 5, lane = tid & 31;
    int wm = wid >> 2, wn = wid & 3;      // 64x32 warp tile
    int n0;
    if (EPI == 5) {
        n0 = 0;
        int sel = blockIdx.x;
        Bh  += sel * 16384;  Bl += sel * 16384;
        bias = (sel == 0) ? bias : (sel == 1) ? bias2 : bias3;
        Cf   = (sel == 0) ? Cf   : (sel == 1) ? Cf2   : Cf3;
    } else {
        n0 = blockIdx.x * 128;
    }
    int mt0 = blockIdx.y;

    stage_async(Bh + (size_t)n0 * lda, lda, sBh, tid);
    stage_async(Bl + (size_t)n0 * lda, lda, sBl, tid);
    if (mt0 < mTiles) {
        stage_async(Ah + (size_t)(mt0 * 128) * lda, lda, sb + 2 * PLANE, tid);
        stage_async(Al + (size_t)(mt0 * 128) * lda, lda, sb + 3 * PLANE, tid);
    }
    CP_COMMIT();
    CP_WAIT0();
    __syncthreads();

    const uint32_t aoff = ((wm * 64 + (lane & 15)) * PAD + (lane >> 4) * 8) * 2;
    const uint32_t boff = ((wn * 32 + ((lane >> 4) << 3) + (lane & 7)) * PAD
                          + ((lane >> 3) & 1) * 8) * 2;

    int buf = 0;
    for (int mt = mt0; mt < mTiles; mt += gridDim.y) {
        int m0 = mt * 128;
        int next = mt + gridDim.y;
        if (next < mTiles) {
            uint32_t nb = sb + (2 + 2 * (buf ^ 1)) * PLANE;
            stage_async(Ah + (size_t)(next * 128) * lda, lda, nb, tid);
            stage_async(Al + (size_t)(next * 128) * lda, lda, nb + PLANE, tid);
            CP_COMMIT();
        }
        const uint32_t sAh = sb + (2 + 2 * buf) * PLANE, sAl = sAh + PLANE;

        float acc[4][4][4];
#pragma unroll
        for (int mi = 0; mi < 4; ++mi)
#pragma unroll
            for (int ni = 0; ni < 4; ++ni)
#pragma unroll
                for (int e = 0; e < 4; ++e) acc[mi][ni][e] = 0.f;

        mma_chunk(acc, sAh, sAl, sBh, sBl, aoff, boff);

        int gp = lane >> 2, t4 = lane & 3;
#pragma unroll
        for (int mi = 0; mi < 4; ++mi) {
            int mrow = m0 + wm * 64 + mi * 16 + gp;
#pragma unroll
            for (int ni = 0; ni < 4; ++ni) {
                int ncol = n0 + wn * 32 + ni * 8 + t4 * 2;
                float d0 = acc[mi][ni][0], d1 = acc[mi][ni][1];
                float d2 = acc[mi][ni][2], d3 = acc[mi][ni][3];
                float b0 = bias[ncol], b1 = bias[ncol + 1];
                d0 += b0; d1 += b1; d2 += b0; d3 += b1;
                size_t ci0 = (size_t)mrow * ldc + ncol;
                size_t ci1 = (size_t)(mrow + 8) * ldc + ncol;
                if (EPI == 1) {
                    d0 = 0.5f * d0 * (1.f + erff(d0 * 0.7071067811865476f));
                    d1 = 0.5f * d1 * (1.f + erff(d1 * 0.7071067811865476f));
                    d2 = 0.5f * d2 * (1.f + erff(d2 * 0.7071067811865476f));
                    d3 = 0.5f * d3 * (1.f + erff(d3 * 0.7071067811865476f));
                    __nv_bfloat16 h0 = __float2bfloat16(d0), h1 = __float2bfloat16(d1);
                    __nv_bfloat16 h2 = __float2bfloat16(d2), h3 = __float2bfloat16(d3);
                    *(__nv_bfloat162*)(Chh + ci0) = __halves2bfloat162(h0, h1);
                    *(__nv_bfloat162*)(Chh + ci1) = __halves2bfloat162(h2, h3);
                    *(__nv_bfloat162*)(Chl + ci0) = __halves2bfloat162(
                        __float2bfloat16(d0 - __bfloat162float(h0)),
                        __float2bfloat16(d1 - __bfloat162float(h1)));
                    *(__nv_bfloat162*)(Chl + ci1) = __halves2bfloat162(
                        __float2bfloat16(d2 - __bfloat162float(h2)),
                        __float2bfloat16(d3 - __bfloat162float(h3)));
                } else {
                    if (EPI == 2) {
                        float2 r0 = *(const float2*)(res + ci0);
                        float2 r1 = *(const float2*)(res + ci1);
                        d0 += r0.x; d1 += r0.y; d2 += r1.x; d3 += r1.y;
                    }
                    *(float2*)(Cf + ci0) = make_float2(d0, d1);
                    *(float2*)(Cf + ci1) = make_float2(d2, d3);
                }
            }
        }
        if (next < mTiles) CP_WAIT0();
        __syncthreads();
        buf ^= 1;
    }
}

// ---------------------------------------------------------------------------
// W2 GEMM (K=512): in-kernel 4-chunk loop. out = acc + bias + res.
// ---------------------------------------------------------------------------
__global__ void __launch_bounds__(256) tgemm_w2(
    const __nv_bfloat16* __restrict__ Ah, const __nv_bfloat16* __restrict__ Al,
    const __nv_bfloat16* __restrict__ Bh, const __nv_bfloat16* __restrict__ Bl,
    const float* __restrict__ bias, const float* __restrict__ res,
    float* __restrict__ Cf, int mTiles)
{
    extern __shared__ char smraw[];
    uint32_t sb = smem_u32(smraw);
    const uint32_t sAh = sb, sAl = sb + PLANE, sBh = sb + 2 * PLANE, sBl = sb + 3 * PLANE;
    const int lda = FFx, ldc = Dx;

    int tid = threadIdx.x, wid = tid >> 5, lane = tid & 31;
    int wm = wid >> 2, wn = wid & 3;

    const uint32_t aoff = ((wm * 64 + (lane & 15)) * PAD + (lane >> 4) * 8) * 2;
    const uint32_t boff = ((wn * 32 + ((lane >> 4) << 3) + (lane & 7)) * PAD
                          + ((lane >> 3) & 1) * 8) * 2;

    for (int mt = blockIdx.y; mt < mTiles; mt += gridDim.y) {
        int m0 = mt * 128;
        float acc[4][4][4];
#pragma unroll
        for (int mi = 0; mi < 4; ++mi)
#pragma unroll
            for (int ni = 0; ni < 4; ++ni)
#pragma unroll
                for (int e = 0; e < 4; ++e) acc[mi][ni][e] = 0.f;

        for (int c = 0; c < 4; ++c) {
            __syncthreads();
            stage_async(Bh + c * 128, lda, sBh, tid);
            stage_async(Bl + c * 128, lda, sBl, tid);
            stage_async(Ah + (size_t)m0 * lda + c * 128, lda, sAh, tid);
            stage_async(Al + (size_t)m0 * lda + c * 128, lda, sAl, tid);
            CP_COMMIT();
            CP_WAIT0();
            __syncthreads();

            mma_chunk(acc, sAh, sAl, sBh, sBl, aoff, boff);
        }

        int gp = lane >> 2, t4 = lane & 3;
#pragma unroll
        for (int mi = 0; mi < 4; ++mi) {
            int mrow = m0 + wm * 64 + mi * 16 + gp;
#pragma unroll
            for (int ni = 0; ni < 4; ++ni) {
                int ncol = wn * 32 + ni * 8 + t4 * 2;
                float d0 = acc[mi][ni][0], d1 = acc[mi][ni][1];
                float d2 = acc[mi][ni][2], d3 = acc[mi][ni][3];
                float b0 = bias[ncol], b1 = bias[ncol + 1];
                size_t ci0 = (size_t)mrow * ldc + ncol;
                size_t ci1 = (size_t)(mrow + 8) * ldc + ncol;
                float2 r0 = *(const float2*)(res + ci0);
                float2 r1 = *(const float2*)(res + ci1);
                *(float2*)(Cf + ci0) = make_float2(d0 + b0 + r0.x, d1 + b1 + r0.y);
                *(float2*)(Cf + ci1) = make_float2(d2 + b0 + r1.x, d3 + b1 + r1.y);
            }
        }
        __syncthreads();
    }
}

// ---------------------------------------------------------------------------
// Fused masked attention, 2 queries/warp pass, vectorized smem access.
// ---------------------------------------------------------------------------
#define AKS 36
#define AVS 204
#define ATTN_SMEM_FLOATS (200*AKS + 32*AVS + 200 + 8*2*AVS)
#define ATTN_SMEM_BYTES  (ATTN_SMEM_FLOATS * 4)

__global__ void __launch_bounds__(256) attn_k(
    const float* __restrict__ Q, const float* __restrict__ Kx,
    const float* __restrict__ Vx, const int* __restrict__ seqs,
    __nv_bfloat16* __restrict__ Oh, __nv_bfloat16* __restrict__ Ol)
{
    int h = blockIdx.x, b = blockIdx.y;
    extern __shared__ float sm[];
    float* Ks   = sm;                    // [200][36]
    float* Vt   = Ks + 200 * AKS;        // [32][204] transposed
    float* flag = Vt + 32 * AVS;         // [200]
    float* ps   = flag + 200;            // [8 warps][2 queries][204]

    int tid = threadIdx.x;
    size_t base = ((size_t)b * Lx) * Dx + h * DKx;

    for (int idx = tid; idx < 1600; idx += 256) {
        int l = idx >> 3, i = idx & 7;
        float4 v = *(const float4*)(Kx + base + (size_t)l * Dx + i * 4);
        *(float4*)(Ks + l * AKS + i * 4) = v;
    }
    for (int idx = tid; idx < 6400; idx += 256) {
        int l = idx >> 5, d = idx & 31;
        Vt[d * AVS + l] = Vx[base + (size_t)l * Dx + d];
    }
    for (int l = tid; l < 200; l += 256)
        flag[l] = (seqs[b * Lx + l] > 0) ? 1.f : 0.f;
    __syncthreads();

    int warp = tid >> 5, lane = tid & 31;
    float* psw = ps + warp * 2 * AVS;
    const float scale = 0.17677669529663687f;

    for (int qp = warp; qp < 100; qp += 8) {
        int q0 = qp, q1 = qp + 100;
        float4 qa[8], qb[8];
        const float4* q0p = (const float4*)(Q + base + (size_t)q0 * Dx);
        const float4* q1p = (const float4*)(Q + base + (size_t)q1 * Dx);
#pragma unroll
        for (int i = 0; i < 8; ++i) { qa[i] = q0p[i]; qb[i] = q1p[i]; }

        float s0[7], s1[7], mx0 = -1e30f, mx1 = -1e30f;
#pragma unroll
        for (int j = 0; j < 7; ++j) {
            int k = j * 32 + lane;
            const float* kr = Ks + k * AKS;
            float d0 = 0.f, d1 = 0.f;
#pragma unroll
            for (int i = 0; i < 8; ++i) {
                float4 kv = *(const float4*)(kr + i * 4);
                d0 = fmaf(qa[i].x, kv.x, d0); d0 = fmaf(qa[i].y, kv.y, d0);
                d0 = fmaf(qa[i].z, kv.z, d0); d0 = fmaf(qa[i].w, kv.w, d0);
                d1 = fmaf(qb[i].x, kv.x, d1); d1 = fmaf(qb[i].y, kv.y, d1);
                d1 = fmaf(qb[i].z, kv.z, d1); d1 = fmaf(qb[i].w, kv.w, d1);
            }
            bool valid = (k < 200);
            float fl = valid ? flag[k] : 0.f;
            float v0 = (fl != 0.f) ? d0 * scale : -1e9f;
            float v1 = (fl != 0.f) ? d1 * scale : -1e9f;
            s0[j] = valid ? v0 : -1e30f;
            s1[j] = valid ? v1 : -1e30f;
            mx0 = fmaxf(mx0, s0[j]);
            mx1 = fmaxf(mx1, s1[j]);
        }
#pragma unroll
        for (int o = 16; o; o >>= 1) {
            mx0 = fmaxf(mx0, __shfl_xor_sync(~0u, mx0, o));
            mx1 = fmaxf(mx1, __shfl_xor_sync(~0u, mx1, o));
        }

        float p0[7], p1[7], sum0 = 0.f, sum1 = 0.f;
#pragma unroll
        for (int j = 0; j < 7; ++j) {
            p0[j] = expf(s0[j] - mx0); sum0 += p0[j];
            p1[j] = expf(s1[j] - mx1); sum1 += p1[j];
        }
#pragma unroll
        for (int o = 16; o; o >>= 1) {
            sum0 += __shfl_xor_sync(~0u, sum0, o);
            sum1 += __shfl_xor_sync(~0u, sum1, o);
        }
        float inv0 = 1.f / sum0, inv1 = 1.f / sum1;

#pragma unroll
        for (int j = 0; j < 7; ++j) {
            int k = j * 32 + lane;
            if (k < 200) { psw[k] = p0[j]; psw[AVS + k] = p1[j]; }
        }
        __syncwarp();

        float a0 = 0.f, a1 = 0.f;
        const float* vr = Vt + lane * AVS;
#pragma unroll
        for (int kg = 0; kg < 50; ++kg) {
            float4 pv0 = *(const float4*)(psw + kg * 4);
            float4 pv1 = *(const float4*)(psw + AVS + kg * 4);
            float4 vv  = *(const float4*)(vr + kg * 4);
            a0 = fmaf(pv0.x, vv.x, a0); a0 = fmaf(pv0.y, vv.y, a0);
            a0 = fmaf(pv0.z, vv.z, a0); a0 = fmaf(pv0.w, vv.w, a0);
            a1 = fmaf(pv1.x, vv.x, a1); a1 = fmaf(pv1.y, vv.y, a1);
            a1 = fmaf(pv1.z, vv.z, a1); a1 = fmaf(pv1.w, vv.w, a1);
        }
        float vo0 = a0 * inv0, vo1 = a1 * inv1;
        __nv_bfloat16 h0 = __float2bfloat16(vo0), h1 = __float2bfloat16(vo1);
        Oh[base + (size_t)q0 * Dx + lane] = h0;
        Ol[base + (size_t)q0 * Dx + lane] = __float2bfloat16(vo0 - __bfloat162float(h0));
        Oh[base + (size_t)q1 * Dx + lane] = h1;
        Ol[base + (size_t)q1 * Dx + lane] = __float2bfloat16(vo1 - __bfloat162float(h1));
        __syncwarp();
    }
}

// ---------------------------------------------------------------------------
// fp32 SGEMM (final FC split-K, raw partials)
// ---------------------------------------------------------------------------
__global__ void __launch_bounds__(256) gemm_fc(
    const float* __restrict__ A, int lda,
    const float* __restrict__ B, int ldb,
    float* __restrict__ C, int ldc, int M, int kChunk)
{
    __shared__ float As[16][128];
    __shared__ float Bs[16][128];
    const int tid = threadIdx.x;
    const int m0 = blockIdx.y * 128, n0 = blockIdx.x * 128;
    const int kStart = blockIdx.z * kChunk;
    const float* Ap = A + (size_t)m0 * lda + kStart;
    const float* Bp = B + (size_t)kStart * ldb + n0;
    const int tx = tid & 15, ty = tid >> 4;
    const int arow = tid >> 2, acol = (tid & 3) << 2;
    const int brow = tid >> 5, bcol = (tid & 31) << 2;

    float acc[8][8];
#pragma unroll
    for (int i = 0; i < 8; ++i)
#pragma unroll
        for (int j = 0; j < 8; ++j) acc[i][j] = 0.f;

    for (int kt = 0; kt < kChunk; kt += 16) {
        float4 a0 = *(const float4*)(Ap + (size_t)arow        * lda + kt + acol);
        float4 a1 = *(const float4*)(Ap + (size_t)(arow + 64) * lda + kt + acol);
        float4 b0 = *(const float4*)(Bp + (size_t)(kt + brow)     * ldb + bcol);
        float4 b1 = *(const float4*)(Bp + (size_t)(kt + brow + 8) * ldb + bcol);
        __syncthreads();
        As[acol + 0][arow] = a0.x; As[acol + 1][arow] = a0.y;
        As[acol + 2][arow] = a0.z; As[acol + 3][arow] = a0.w;
        As[acol + 0][arow + 64] = a1.x; As[acol + 1][arow + 64] = a1.y;
        As[acol + 2][arow + 64] = a1.z; As[acol + 3][arow + 64] = a1.w;
        *(float4*)&Bs[brow][bcol] = b0;
        *(float4*)&Bs[brow + 8][bcol] = b1;
        __syncthreads();
#pragma unroll
        for (int kk = 0; kk < 16; ++kk) {
            float a[8], bb[8];
            *(float4*)(a)      = *(const float4*)&As[kk][ty * 8];
            *(float4*)(a + 4)  = *(const float4*)&As[kk][ty * 8 + 4];
            *(float4*)(bb)     = *(const float4*)&Bs[kk][tx * 8];
            *(float4*)(bb + 4) = *(const float4*)&Bs[kk][tx * 8 + 4];
#pragma unroll
            for (int i = 0; i < 8; ++i)
#pragma unroll
                for (int j = 0; j < 8; ++j)
                    acc[i][j] = fmaf(a[i], bb[j], acc[i][j]);
        }
    }

    float* Cp = C + (size_t)blockIdx.z * M * ldc;
#pragma unroll
    for (int i = 0; i < 8; ++i) {
        int m = m0 + ty * 8 + i;
#pragma unroll
        for (int j = 0; j < 8; j += 4) {
            int n = n0 + tx * 8 + j;
            *(float4*)(Cp + (size_t)m * ldc + n) =
                make_float4(acc[i][j], acc[i][j+1], acc[i][j+2], acc[i][j+3]);
        }
    }
}

__global__ void fcred_k(const float* __restrict__ part, const float* __restrict__ bias,
                        float* __restrict__ out) {
    int idx = blockIdx.x * 256 + threadIdx.x;
    if (idx >= Bx * Dx) return;
    float s = 0.f;
#pragma unroll
    for (int z = 0; z < FC_SPLIT; ++z) s += part[(size_t)z * Bx * Dx + idx];
    out[idx] = s + bias[idx & (Dx - 1)];
}

// ---------------------------------------------------------------------------
// Host driver (graph-capturable: kernel launches only)
// ---------------------------------------------------------------------------
extern "C" void kernel_launch(void* const* d_in, const int* in_sizes, int n_in,
                              void* d_out, int out_size) {
    (void)in_sizes; (void)n_in; (void)out_size;
    const int*   seqs = (const int*)  d_in[0];
    const float* tok  = (const float*)d_in[1];
    const float* pos  = (const float*)d_in[2];
    const float* Wq   = (const float*)d_in[3];
    const float* bq   = (const float*)d_in[4];
    const float* Wk   = (const float*)d_in[5];
    const float* bk   = (const float*)d_in[6];
    const float* Wv   = (const float*)d_in[7];
    const float* bv   = (const float*)d_in[8];
    const float* Wo   = (const float*)d_in[9];
    const float* bo   = (const float*)d_in[10];
    const float* ln1w = (const float*)d_in[11];
    const float* ln1b = (const float*)d_in[12];
    const float* ln2w = (const float*)d_in[13];
    const float* ln2b = (const float*)d_in[14];
    const float* W1   = (const float*)d_in[15];
    const float* b1   = (const float*)d_in[16];
    const float* W2   = (const float*)d_in[17];
    const float* b2   = (const float*)d_in[18];
    const float* fcW  = (const float*)d_in[19];
    const float* fcb  = (const float*)d_in[20];
    float* out = (float*)d_out;

    float *px, *pq, *pk, *pv, *pp;
    __nv_bfloat16 *ah, *al, *oh, *ol, *fh, *fl, *wh, *wl;
    cudaGetSymbolAddress((void**)&px, g_x);
    cudaGetSymbolAddress((void**)&pq, g_q);
    cudaGetSymbolAddress((void**)&pk, g_k);
    cudaGetSymbolAddress((void**)&pv, g_v);
    cudaGetSymbolAddress((void**)&pp, g_fcp);
    cudaGetSymbolAddress((void**)&ah, g_ah);
    cudaGetSymbolAddress((void**)&al, g_al);
    cudaGetSymbolAddress((void**)&oh, g_oh);
    cudaGetSymbolAddress((void**)&ol, g_ol);
    cudaGetSymbolAddress((void**)&fh, g_fh);
    cudaGetSymbolAddress((void**)&fl, g_fl);
    cudaGetSymbolAddress((void**)&wh, g_wh);
    cudaGetSymbolAddress((void**)&wl, g_wl);

    cudaFuncSetAttribute(attn_k, cudaFuncAttributeMaxDynamicSharedMemorySize, ATTN_SMEM_BYTES);
    cudaFuncSetAttribute(tgemm<1>, cudaFuncAttributeMaxDynamicSharedMemorySize, TG_SMEM);
    cudaFuncSetAttribute(tgemm<2>, cudaFuncAttributeMaxDynamicSharedMemorySize, TG_SMEM);
    cudaFuncSetAttribute(tgemm<5>, cudaFuncAttributeMaxDynamicSharedMemorySize, TG_SMEM);
    cudaFuncSetAttribute(tgemm_w2, cudaFuncAttributeMaxDynamicSharedMemorySize, W2_SMEM);

    // --- weight transpose + split: ONE launch for everything ---
    wconv_all<<<(NLx * LW + 255) / 256, 256>>>(Wq, Wk, Wv, Wo, W1, W2, wh, wl);

    const dim3 gRow(NT / 8);
    const int  MT = NT / 128;  // 1600

    embed_k<<<gRow, 256>>>(seqs, tok, pos, px);

    for (int i = 0; i < NLx; ++i) {
        size_t wb = (size_t)i * LW;
        // --- attention block ---
        ln_k<<<gRow, 256>>>(px, ln1w + i * Dx, ln1b + i * Dx, ah, al);
        tgemm<5><<<dim3(3,148), 256, TG_SMEM>>>(ah, al, Dx, wh + wb, wl + wb,
                 bq + i*Dx, bk + i*Dx, bv + i*Dx, nullptr,
                 pq, pk, pv, nullptr, nullptr, Dx, MT);
        attn_k<<<dim3(Hx, Bx), 256, ATTN_SMEM_BYTES>>>(pq, pk, pv, seqs, oh, ol);
        tgemm<2><<<dim3(1,148), 256, TG_SMEM>>>(oh, ol, Dx, wh + wb + 49152, wl + wb + 49152,
                 bo + i*Dx, nullptr, nullptr, px,
                 px, nullptr, nullptr, nullptr, nullptr, Dx, MT);
        // --- FFN block ---
        ln_k<<<gRow, 256>>>(px, ln2w + i * Dx, ln2b + i * Dx, ah, al);
        tgemm<1><<<dim3(4,37), 256, TG_SMEM>>>(ah, al, Dx, wh + wb + 65536, wl + wb + 65536,
                 b1 + i*FFx, nullptr, nullptr, nullptr,
                 nullptr, nullptr, nullptr, fh, fl, FFx, MT);
        tgemm_w2<<<dim3(1,148), 256, W2_SMEM>>>(fh, fl, wh + wb + 131072, wl + wb + 131072,
                 b2 + i*Dx, px, px, MT);
    }

    // Final FC (fp32 split-K, deterministic reduce)
    gemm_fc<<<dim3(1, Bx / 128, FC_SPLIT), 256>>>(
        px, Lx * Dx, fcW, Dx, pp, Dx, Bx, (Lx * Dx) / FC_SPLIT);
    fcred_k<<<(Bx * Dx + 255) / 256, 256>>>(pp, fcb, out);
}

// round 14
// speedup vs baseline: 1.0424x; 1.0250x over previous
#include <cuda_runtime.h>
#include <cuda_bf16.h>
#include <math.h>
#include <stdint.h>

// Problem constants
#define Bx   1024
#define Lx   200
#define Dx   128
#define Hx   4
#define DKx  32
#define FFx  512
#define NLx  2
#define NT   (Bx*Lx)          // 204800 tokens
#define FCK  (Lx*Dx)          // 25600
#define FCZ  25               // FC K-split (25 x 1024)

// ---------------------------------------------------------------------------
// Device-global scratch (allocation-free rule).
// ---------------------------------------------------------------------------
__device__ float g_x  [(size_t)NT * Dx];    // residual stream (fp32)
__device__ float g_q  [(size_t)NT * Dx];
__device__ float g_k  [(size_t)NT * Dx];
__device__ float g_v  [(size_t)NT * Dx];
__device__ float g_fcp[(size_t)32 * Bx * Dx];

// bf16 hi/lo activation planes
__device__ __nv_bfloat16 g_ah[(size_t)NT * Dx],  g_al[(size_t)NT * Dx];   // LN out / FC split
__device__ __nv_bfloat16 g_oh[(size_t)NT * Dx],  g_ol[(size_t)NT * Dx];   // attn out
__device__ __nv_bfloat16 g_fh[(size_t)NT * FFx], g_fl[(size_t)NT * FFx];  // FFN mid

// transposed+split weights [N][K]: per layer q(16384) k v o w1(65536) w2(65536)
#define LW 196608
__device__ __nv_bfloat16 g_wh[(size_t)NLx * LW], g_wl[(size_t)NLx * LW];
// FC weight transposed+split [128][25600]
__device__ __nv_bfloat16 g_fcwh[(size_t)Dx * FCK], g_fcwl[(size_t)Dx * FCK];

// ---------------------------------------------------------------------------
// Baseline-PTX tensor core helpers
// ---------------------------------------------------------------------------
__device__ __forceinline__ uint32_t smem_u32(const void* p) {
    uint32_t a;
    asm("{ .reg .u64 t; cvta.to.shared.u64 t, %1; cvt.u32.u64 %0, t; }" : "=r"(a) : "l"(p));
    return a;
}
__device__ __forceinline__ void ldm4(uint32_t* r, uint32_t addr) {
    asm volatile("ldmatrix.sync.aligned.m8n8.x4.shared.b16 {%0,%1,%2,%3}, [%4];"
                 : "=r"(r[0]), "=r"(r[1]), "=r"(r[2]), "=r"(r[3]) : "r"(addr));
}
__device__ __forceinline__ void mma_bf16(float* d, const uint32_t* a, const uint32_t* b) {
    asm volatile("mma.sync.aligned.m16n8k16.row.col.f32.bf16.bf16.f32 "
                 "{%0,%1,%2,%3}, {%4,%5,%6,%7}, {%8,%9}, {%0,%1,%2,%3};"
                 : "+f"(d[0]), "+f"(d[1]), "+f"(d[2]), "+f"(d[3])
                 : "r"(a[0]), "r"(a[1]), "r"(a[2]), "r"(a[3]), "r"(b[0]), "r"(b[1]));
}
#define CP_COMMIT() asm volatile("cp.async.commit_group;" ::: "memory")
#define CP_WAIT0()  asm volatile("cp.async.wait_group 0;" ::: "memory")

// ---------------------------------------------------------------------------
// Weight transpose + bf16 split (single launch, all layer weights)
// ---------------------------------------------------------------------------
__global__ void wconv_all(const float* __restrict__ Wq, const float* __restrict__ Wk,
                          const float* __restrict__ Wv, const float* __restrict__ Wo,
                          const float* __restrict__ W1, const float* __restrict__ W2,
                          __nv_bfloat16* __restrict__ Th, __nv_bfloat16* __restrict__ Tl) {
    int idx = blockIdx.x * 256 + threadIdx.x;
    if (idx >= NLx * LW) return;
    int l = idx / LW, o = idx % LW;
    float v;
    if (o < 65536) {
        int seg = o >> 14, loc = o & 16383;
        int n = loc >> 7, k = loc & 127;
        const float* W = (seg == 0) ? Wq : (seg == 1) ? Wk : (seg == 2) ? Wv : Wo;
        v = W[(size_t)l * Dx * Dx + k * Dx + n];
    } else if (o < 131072) {
        int loc = o - 65536;
        int n = loc >> 7, k = loc & 127;
        v = W1[(size_t)l * Dx * FFx + k * FFx + n];
    } else {
        int loc = o - 131072;
        int n = loc >> 9, k = loc & 511;
        v = W2[(size_t)l * FFx * Dx + k * Dx + n];
    }
    __nv_bfloat16 h = __float2bfloat16(v);
    Th[idx] = h;
    Tl[idx] = __float2bfloat16(v - __bfloat162float(h));
}

// FC weight: T[n*FCK+k] = fcW[k*Dx+n], hi/lo split
__global__ void wconv_fc(const float* __restrict__ W,
                         __nv_bfloat16* __restrict__ Th, __nv_bfloat16* __restrict__ Tl) {
    int idx = blockIdx.x * 256 + threadIdx.x;
    if (idx >= Dx * FCK) return;
    int n = idx / FCK, k = idx % FCK;
    float v = W[(size_t)k * Dx + n];
    __nv_bfloat16 h = __float2bfloat16(v);
    Th[idx] = h;
    Tl[idx] = __float2bfloat16(v - __bfloat162float(h));
}

// fp32 -> bf16 hi/lo planes (for FC input)
__global__ void xsplit_k(const float* __restrict__ x,
                         __nv_bfloat16* __restrict__ xh, __nv_bfloat16* __restrict__ xl) {
    int idx = blockIdx.x * 256 + threadIdx.x;
    float v = x[idx];
    __nv_bfloat16 h = __float2bfloat16(v);
    xh[idx] = h;
    xl[idx] = __float2bfloat16(v - __bfloat162float(h));
}

// ---------------------------------------------------------------------------
// Embedding
// ---------------------------------------------------------------------------
__global__ void embed_k(const int* __restrict__ seqs, const float* __restrict__ tok,
                        const float* __restrict__ pos, float* __restrict__ x) {
    int t = blockIdx.x * 8 + (threadIdx.x >> 5);
    int lane = threadIdx.x & 31;
    if (t >= NT) return;
    int id = seqs[t], l = t % Lx;
    float4 te = *(const float4*)(tok + (size_t)id * Dx + lane * 4);
    float4 pe = *(const float4*)(pos + (size_t)l  * Dx + lane * 4);
    *(float4*)(x + (size_t)t * Dx + lane * 4) =
        make_float4(te.x + pe.x, te.y + pe.y, te.z + pe.z, te.w + pe.w);
}

// ---------------------------------------------------------------------------
// LayerNorm -> bf16 hi/lo planes
// ---------------------------------------------------------------------------
__global__ void ln_k(const float* __restrict__ x, const float* __restrict__ w,
                     const float* __restrict__ b,
                     __nv_bfloat16* __restrict__ oh, __nv_bfloat16* __restrict__ ol) {
    int r = blockIdx.x * 8 + (threadIdx.x >> 5);
    int lane = threadIdx.x & 31;
    if (r >= NT) return;
    float4 v = *(const float4*)(x + (size_t)r * Dx + lane * 4);
    float s = v.x + v.y + v.z + v.w;
#pragma unroll
    for (int o = 16; o; o >>= 1) s += __shfl_xor_sync(~0u, s, o);
    float mu = s * (1.f / 128.f);
    float dx = v.x - mu, dy = v.y - mu, dz = v.z - mu, dw = v.w - mu;
    float s2 = dx*dx + dy*dy + dz*dz + dw*dw;
#pragma unroll
    for (int o = 16; o; o >>= 1) s2 += __shfl_xor_sync(~0u, s2, o);
    float rs = rsqrtf(s2 * (1.f / 128.f) + 1e-5f);
    float4 wv = *(const float4*)(w + lane * 4);
    float4 bv = *(const float4*)(b + lane * 4);
    float y0 = dx*rs*wv.x + bv.x, y1 = dy*rs*wv.y + bv.y;
    float y2 = dz*rs*wv.z + bv.z, y3 = dw*rs*wv.w + bv.w;
    __nv_bfloat16 h0 = __float2bfloat16(y0), h1 = __float2bfloat16(y1);
    __nv_bfloat16 h2 = __float2bfloat16(y2), h3 = __float2bfloat16(y3);
    __nv_bfloat16 l0 = __float2bfloat16(y0 - __bfloat162float(h0));
    __nv_bfloat16 l1 = __float2bfloat16(y1 - __bfloat162float(h1));
    __nv_bfloat16 l2 = __float2bfloat16(y2 - __bfloat162float(h2));
    __nv_bfloat16 l3 = __float2bfloat16(y3 - __bfloat162float(h3));
    size_t o = (size_t)r * Dx + lane * 4;
    *(__nv_bfloat162*)(oh + o)     = __halves2bfloat162(h0, h1);
    *(__nv_bfloat162*)(oh + o + 2) = __halves2bfloat162(h2, h3);
    *(__nv_bfloat162*)(ol + o)     = __halves2bfloat162(l0, l1);
    *(__nv_bfloat162*)(ol + o + 2) = __halves2bfloat162(l2, l3);
}

// ---------------------------------------------------------------------------
// GEMM tiles/layout
// ---------------------------------------------------------------------------
#define PAD 136
#define PLANE (128 * PAD * 2)       // 34816 bytes (K=128 rows)
#define TG_SMEM (6 * PLANE)         // 208896 bytes
#define PAD2 72
#define HPLANE (128 * PAD2 * 2)     // 18432 bytes (K=64 rows)
#define W2_SMEM (8 * HPLANE)        // 147456 bytes (2 buffers x 4 half-planes)

__device__ __forceinline__ void stage_async(const __nv_bfloat16* __restrict__ src, int ld,
                                            uint32_t smbase, int tid) {
#pragma unroll
    for (int it = 0; it < 8; ++it) {
        int i = it * 256 + tid;
        int row = i >> 4, seg = (i & 15) << 3;
        uint32_t dst = smbase + (row * PAD + seg) * 2;
        asm volatile("cp.async.cg.shared.global [%0], [%1], 16;"
                     :: "r"(dst), "l"(src + (size_t)row * ld + seg) : "memory");
    }
}

// K=64 chunk staging: 128 rows x 64 cols bf16
__device__ __forceinline__ void stage_async64(const __nv_bfloat16* __restrict__ src, int ld,
                                              uint32_t smbase, int tid) {
#pragma unroll
    for (int it = 0; it < 4; ++it) {
        int i = it * 256 + tid;
        int row = i >> 3, seg = (i & 7) << 3;
        uint32_t dst = smbase + (row * PAD2 + seg) * 2;
        asm volatile("cp.async.cg.shared.global [%0], [%1], 16;"
                     :: "r"(dst), "l"(src + (size_t)row * ld + seg) : "memory");
    }
}

// K=128 chunk MMA (64x32 warp tile)
__device__ __forceinline__ void mma_chunk(
    float acc[4][4][4], uint32_t sAh, uint32_t sAl, uint32_t sBh, uint32_t sBl,
    uint32_t aoff, uint32_t boff)
{
#pragma unroll
    for (int ks = 0; ks < 8; ++ks) {
        uint32_t kb = ks * 32;
        uint32_t fah[4][4], fal[4][4], fbh[4][2], fbl[4][2];
#pragma unroll
        for (int mi = 0; mi < 4; ++mi) {
            uint32_t ro = mi * 16 * PAD * 2 + kb;
            ldm4(fah[mi], sAh + aoff + ro);
            ldm4(fal[mi], sAl + aoff + ro);
        }
#pragma unroll
        for (int np = 0; np < 2; ++np) {
            uint32_t ro = np * 16 * PAD * 2 + kb;
            ldm4(&fbh[2 * np][0], sBh + boff + ro);
            ldm4(&fbl[2 * np][0], sBl + boff + ro);
        }
#pragma unroll
        for (int mi = 0; mi < 4; ++mi)
#pragma unroll
            for (int ni = 0; ni < 4; ++ni) {
                mma_bf16(acc[mi][ni], fah[mi], fbh[ni]);
                mma_bf16(acc[mi][ni], fah[mi], fbl[ni]);
                mma_bf16(acc[mi][ni], fal[mi], fbh[ni]);
            }
    }
}

// K=64 chunk MMA (PAD2 layout)
__device__ __forceinline__ void mma_chunk64(
    float acc[4][4][4], uint32_t sAh, uint32_t sAl, uint32_t sBh, uint32_t sBl,
    uint32_t aoff, uint32_t boff)
{
#pragma unroll
    for (int ks = 0; ks < 4; ++ks) {
        uint32_t kb = ks * 32;
        uint32_t fah[4][4], fal[4][4], fbh[4][2], fbl[4][2];
#pragma unroll
        for (int mi = 0; mi < 4; ++mi) {
            uint32_t ro = mi * 16 * PAD2 * 2 + kb;
            ldm4(fah[mi], sAh + aoff + ro);
            ldm4(fal[mi], sAl + aoff + ro);
        }
#pragma unroll
        for (int np = 0; np < 2; ++np) {
            uint32_t ro = np * 16 * PAD2 * 2 + kb;
            ldm4(&fbh[2 * np][0], sBh + boff + ro);
            ldm4(&fbl[2 * np][0], sBl + boff + ro);
        }
#pragma unroll
        for (int mi = 0; mi < 4; ++mi)
#pragma unroll
            for (int ni = 0; ni < 4; ++ni) {
                mma_bf16(acc[mi][ni], fah[mi], fbh[ni]);
                mma_bf16(acc[mi][ni], fah[mi], fbl[ni]);
                mma_bf16(acc[mi][ni], fal[mi], fbh[ni]);
            }
    }
}

// ---------------------------------------------------------------------------
// Pipelined tensor-core GEMM (K=128 resident-B, A double-buffered).
// EPI: 1=gelu(+bias)->bf16; 2=+bias+res->fp32; 5=fused QKV.
// ---------------------------------------------------------------------------
template <int EPI>
__global__ void __launch_bounds__(256) tgemm(
    const __nv_bfloat16* __restrict__ Ah, const __nv_bfloat16* __restrict__ Al, int lda,
    const __nv_bfloat16* __restrict__ Bh, const __nv_bfloat16* __restrict__ Bl,
    const float* __restrict__ bias, const float* __restrict__ bias2,
    const float* __restrict__ bias3, const float* __restrict__ res,
    float* __restrict__ Cf, float* __restrict__ Cf2, float* __restrict__ Cf3,
    __nv_bfloat16* __restrict__ Chh, __nv_bfloat16* __restrict__ Chl,
    int ldc, int mTiles)
{
    extern __shared__ char smraw[];
    uint32_t sb = smem_u32(smraw);
    const uint32_t sBh = sb, sBl = sb + PLANE;

    int tid = threadIdx.x, wid = tid >> 5, lane = tid & 31;
    int wm = wid >> 2, wn = wid & 3;
    int n0;
    if (EPI == 5) {
        n0 = 0;
        int sel = blockIdx.x;
        Bh  += sel * 16384;  Bl += sel * 16384;
        bias = (sel == 0) ? bias : (sel == 1) ? bias2 : bias3;
        Cf   = (sel == 0) ? Cf   : (sel == 1) ? Cf2   : Cf3;
    } else {
        n0 = blockIdx.x * 128;
    }
    int mt0 = blockIdx.y;

    stage_async(Bh + (size_t)n0 * lda, lda, sBh, tid);
    stage_async(Bl + (size_t)n0 * lda, lda, sBl, tid);
    if (mt0 < mTiles) {
        stage_async(Ah + (size_t)(mt0 * 128) * lda, lda, sb + 2 * PLANE, tid);
        stage_async(Al + (size_t)(mt0 * 128) * lda, lda, sb + 3 * PLANE, tid);
    }
    CP_COMMIT();
    CP_WAIT0();
    __syncthreads();

    const uint32_t aoff = ((wm * 64 + (lane & 15)) * PAD + (lane >> 4) * 8) * 2;
    const uint32_t boff = ((wn * 32 + ((lane >> 4) << 3) + (lane & 7)) * PAD
                          + ((lane >> 3) & 1) * 8) * 2;

    int buf = 0;
    for (int mt = mt0; mt < mTiles; mt += gridDim.y) {
        int m0 = mt * 128;
        int next = mt + gridDim.y;
        if (next < mTiles) {
            uint32_t nb = sb + (2 + 2 * (buf ^ 1)) * PLANE;
            stage_async(Ah + (size_t)(next * 128) * lda, lda, nb, tid);
            stage_async(Al + (size_t)(next * 128) * lda, lda, nb + PLANE, tid);
            CP_COMMIT();
        }
        const uint32_t sAh = sb + (2 + 2 * buf) * PLANE, sAl = sAh + PLANE;

        float acc[4][4][4];
#pragma unroll
        for (int mi = 0; mi < 4; ++mi)
#pragma unroll
            for (int ni = 0; ni < 4; ++ni)
#pragma unroll
                for (int e = 0; e < 4; ++e) acc[mi][ni][e] = 0.f;

        mma_chunk(acc, sAh, sAl, sBh, sBl, aoff, boff);

        int gp = lane >> 2, t4 = lane & 3;
#pragma unroll
        for (int mi = 0; mi < 4; ++mi) {
            int mrow = m0 + wm * 64 + mi * 16 + gp;
#pragma unroll
            for (int ni = 0; ni < 4; ++ni) {
                int ncol = n0 + wn * 32 + ni * 8 + t4 * 2;
                float d0 = acc[mi][ni][0], d1 = acc[mi][ni][1];
                float d2 = acc[mi][ni][2], d3 = acc[mi][ni][3];
                float b0 = bias[ncol], b1 = bias[ncol + 1];
                d0 += b0; d1 += b1; d2 += b0; d3 += b1;
                size_t ci0 = (size_t)mrow * ldc + ncol;
                size_t ci1 = (size_t)(mrow + 8) * ldc + ncol;
                if (EPI == 1) {
                    d0 = 0.5f * d0 * (1.f + erff(d0 * 0.7071067811865476f));
                    d1 = 0.5f * d1 * (1.f + erff(d1 * 0.7071067811865476f));
                    d2 = 0.5f * d2 * (1.f + erff(d2 * 0.7071067811865476f));
                    d3 = 0.5f * d3 * (1.f + erff(d3 * 0.7071067811865476f));
                    __nv_bfloat16 h0 = __float2bfloat16(d0), h1 = __float2bfloat16(d1);
                    __nv_bfloat16 h2 = __float2bfloat16(d2), h3 = __float2bfloat16(d3);
                    *(__nv_bfloat162*)(Chh + ci0) = __halves2bfloat162(h0, h1);
                    *(__nv_bfloat162*)(Chh + ci1) = __halves2bfloat162(h2, h3);
                    *(__nv_bfloat162*)(Chl + ci0) = __halves2bfloat162(
                        __float2bfloat16(d0 - __bfloat162float(h0)),
                        __float2bfloat16(d1 - __bfloat162float(h1)));
                    *(__nv_bfloat162*)(Chl + ci1) = __halves2bfloat162(
                        __float2bfloat16(d2 - __bfloat162float(h2)),
                        __float2bfloat16(d3 - __bfloat162float(h3)));
                } else {
                    if (EPI == 2) {
                        float2 r0 = *(const float2*)(res + ci0);
                        float2 r1 = *(const float2*)(res + ci1);
                        d0 += r0.x; d1 += r0.y; d2 += r1.x; d3 += r1.y;
                    }
                    *(float2*)(Cf + ci0) = make_float2(d0, d1);
                    *(float2*)(Cf + ci1) = make_float2(d2, d3);
                }
            }
        }
        if (next < mTiles) CP_WAIT0();
        __syncthreads();
        buf ^= 1;
    }
}

// ---------------------------------------------------------------------------
// W2 GEMM (K=512): 8 pipelined K=64 chunks, double-buffered A+B.
// ---------------------------------------------------------------------------
__global__ void __launch_bounds__(256) tgemm_w2(
    const __nv_bfloat16* __restrict__ Ah, const __nv_bfloat16* __restrict__ Al,
    const __nv_bfloat16* __restrict__ Bh, const __nv_bfloat16* __restrict__ Bl,
    const float* __restrict__ bias, const float* __restrict__ res,
    float* __restrict__ Cf, int mTiles)
{
    extern __shared__ char smraw[];
    uint32_t sb = smem_u32(smraw);
    const int lda = FFx, ldc = Dx;

    int tid = threadIdx.x, wid = tid >> 5, lane = tid & 31;
    int wm = wid >> 2, wn = wid & 3;

    const uint32_t aoff = ((wm * 64 + (lane & 15)) * PAD2 + (lane >> 4) * 8) * 2;
    const uint32_t boff = ((wn * 32 + ((lane >> 4) << 3) + (lane & 7)) * PAD2
                          + ((lane >> 3) & 1) * 8) * 2;

    for (int mt = blockIdx.y; mt < mTiles; mt += gridDim.y) {
        int m0 = mt * 128;
        float acc[4][4][4];
#pragma unroll
        for (int mi = 0; mi < 4; ++mi)
#pragma unroll
            for (int ni = 0; ni < 4; ++ni)
#pragma unroll
                for (int e = 0; e < 4; ++e) acc[mi][ni][e] = 0.f;

        // prologue: chunk 0 into buffer 0
        stage_async64(Ah + (size_t)m0 * lda,     lda, sb + 0 * HPLANE, tid);
        stage_async64(Al + (size_t)m0 * lda,     lda, sb + 1 * HPLANE, tid);
        stage_async64(Bh,                        lda, sb + 2 * HPLANE, tid);
        stage_async64(Bl,                        lda, sb + 3 * HPLANE, tid);
        CP_COMMIT();
        CP_WAIT0();
        __syncthreads();

        int buf = 0;
        for (int c = 0; c < 8; ++c) {
            if (c + 1 < 8) {
                uint32_t nb = sb + (buf ^ 1) * 4 * HPLANE;
                int ko = (c + 1) * 64;
                stage_async64(Ah + (size_t)m0 * lda + ko, lda, nb,              tid);
                stage_async64(Al + (size_t)m0 * lda + ko, lda, nb + HPLANE,     tid);
                stage_async64(Bh + ko,                    lda, nb + 2 * HPLANE, tid);
                stage_async64(Bl + ko,                    lda, nb + 3 * HPLANE, tid);
                CP_COMMIT();
            }
            uint32_t cb = sb + buf * 4 * HPLANE;
            mma_chunk64(acc, cb, cb + HPLANE, cb + 2 * HPLANE, cb + 3 * HPLANE, aoff, boff);
            if (c + 1 < 8) CP_WAIT0();
            __syncthreads();
            buf ^= 1;
        }

        int gp = lane >> 2, t4 = lane & 3;
#pragma unroll
        for (int mi = 0; mi < 4; ++mi) {
            int mrow = m0 + wm * 64 + mi * 16 + gp;
#pragma unroll
            for (int ni = 0; ni < 4; ++ni) {
                int ncol = wn * 32 + ni * 8 + t4 * 2;
                float d0 = acc[mi][ni][0], d1 = acc[mi][ni][1];
                float d2 = acc[mi][ni][2], d3 = acc[mi][ni][3];
                float b0 = bias[ncol], b1 = bias[ncol + 1];
                size_t ci0 = (size_t)mrow * ldc + ncol;
                size_t ci1 = (size_t)(mrow + 8) * ldc + ncol;
                float2 r0 = *(const float2*)(res + ci0);
                float2 r1 = *(const float2*)(res + ci1);
                *(float2*)(Cf + ci0) = make_float2(d0 + b0 + r0.x, d1 + b1 + r0.y);
                *(float2*)(Cf + ci1) = make_float2(d2 + b0 + r1.x, d3 + b1 + r1.y);
            }
        }
        __syncthreads();
    }
}

// ---------------------------------------------------------------------------
// Final FC on tensor path: grid (8 m-tiles, 25 k-splits), 16 K=64 chunks each,
// pipelined double-buffer; raw fp32 partials -> fcred.
// ---------------------------------------------------------------------------
__global__ void __launch_bounds__(256) tgemm_fc(
    const __nv_bfloat16* __restrict__ Ah, const __nv_bfloat16* __restrict__ Al,
    const __nv_bfloat16* __restrict__ Bh, const __nv_bfloat16* __restrict__ Bl,
    float* __restrict__ part)
{
    extern __shared__ char smraw[];
    uint32_t sb = smem_u32(smraw);
    const int lda = FCK;

    int tid = threadIdx.x, wid = tid >> 5, lane = tid & 31;
    int wm = wid >> 2, wn = wid & 3;
    int m0 = blockIdx.x * 128;
    int kbase = blockIdx.y * 1024;

    const uint32_t aoff = ((wm * 64 + (lane & 15)) * PAD2 + (lane >> 4) * 8) * 2;
    const uint32_t boff = ((wn * 32 + ((lane >> 4) << 3) + (lane & 7)) * PAD2
                          + ((lane >> 3) & 1) * 8) * 2;

    float acc[4][4][4];
#pragma unroll
    for (int mi = 0; mi < 4; ++mi)
#pragma unroll
        for (int ni = 0; ni < 4; ++ni)
#pragma unroll
            for (int e = 0; e < 4; ++e) acc[mi][ni][e] = 0.f;

    stage_async64(Ah + (size_t)m0 * lda + kbase, lda, sb + 0 * HPLANE, tid);
    stage_async64(Al + (size_t)m0 * lda + kbase, lda, sb + 1 * HPLANE, tid);
    stage_async64(Bh + kbase,                    lda, sb + 2 * HPLANE, tid);
    stage_async64(Bl + kbase,                    lda, sb + 3 * HPLANE, tid);
    CP_COMMIT();
    CP_WAIT0();
    __syncthreads();

    int buf = 0;
    for (int c = 0; c < 16; ++c) {
        if (c + 1 < 16) {
            uint32_t nb = sb + (buf ^ 1) * 4 * HPLANE;
            int ko = kbase + (c + 1) * 64;
            stage_async64(Ah + (size_t)m0 * lda + ko, lda, nb,              tid);
            stage_async64(Al + (size_t)m0 * lda + ko, lda, nb + HPLANE,     tid);
            stage_async64(Bh + ko,                    lda, nb + 2 * HPLANE, tid);
            stage_async64(Bl + ko,                    lda, nb + 3 * HPLANE, tid);
            CP_COMMIT();
        }
        uint32_t cb = sb + buf * 4 * HPLANE;
        mma_chunk64(acc, cb, cb + HPLANE, cb + 2 * HPLANE, cb + 3 * HPLANE, aoff, boff);
        if (c + 1 < 16) CP_WAIT0();
        __syncthreads();
        buf ^= 1;
    }

    float* Cp = part + (size_t)blockIdx.y * Bx * Dx;
    int gp = lane >> 2, t4 = lane & 3;
#pragma unroll
    for (int mi = 0; mi < 4; ++mi) {
        int mrow = m0 + wm * 64 + mi * 16 + gp;
#pragma unroll
        for (int ni = 0; ni < 4; ++ni) {
            int ncol = wn * 32 + ni * 8 + t4 * 2;
            *(float2*)(Cp + (size_t)mrow * Dx + ncol) =
                make_float2(acc[mi][ni][0], acc[mi][ni][1]);
            *(float2*)(Cp + (size_t)(mrow + 8) * Dx + ncol) =
                make_float2(acc[mi][ni][2], acc[mi][ni][3]);
        }
    }
}

__global__ void fcred_k(const float* __restrict__ part, const float* __restrict__ bias,
                        float* __restrict__ out) {
    int idx = blockIdx.x * 256 + threadIdx.x;
    if (idx >= Bx * Dx) return;
    float s = 0.f;
#pragma unroll
    for (int z = 0; z < FCZ; ++z) s += part[(size_t)z * Bx * Dx + idx];
    out[idx] = s + bias[idx & (Dx - 1)];
}

// ---------------------------------------------------------------------------
// Fused masked attention, 2 queries/warp pass, vectorized smem, __expf.
// ---------------------------------------------------------------------------
#define AKS 36
#define AVS 204
#define ATTN_SMEM_FLOATS (200*AKS + 32*AVS + 200 + 8*2*AVS)
#define ATTN_SMEM_BYTES  (ATTN_SMEM_FLOATS * 4)

__global__ void __launch_bounds__(256) attn_k(
    const float* __restrict__ Q, const float* __restrict__ Kx,
    const float* __restrict__ Vx, const int* __restrict__ seqs,
    __nv_bfloat16* __restrict__ Oh, __nv_bfloat16* __restrict__ Ol)
{
    int h = blockIdx.x, b = blockIdx.y;
    extern __shared__ float sm[];
    float* Ks   = sm;
    float* Vt   = Ks + 200 * AKS;
    float* flag = Vt + 32 * AVS;
    float* ps   = flag + 200;

    int tid = threadIdx.x;
    size_t base = ((size_t)b * Lx) * Dx + h * DKx;

    for (int idx = tid; idx < 1600; idx += 256) {
        int l = idx >> 3, i = idx & 7;
        float4 v = *(const float4*)(Kx + base + (size_t)l * Dx + i * 4);
        *(float4*)(Ks + l * AKS + i * 4) = v;
    }
    for (int idx = tid; idx < 6400; idx += 256) {
        int l = idx >> 5, d = idx & 31;
        Vt[d * AVS + l] = Vx[base + (size_t)l * Dx + d];
    }
    for (int l = tid; l < 200; l += 256)
        flag[l] = (seqs[b * Lx + l] > 0) ? 1.f : 0.f;
    __syncthreads();

    int warp = tid >> 5, lane = tid & 31;
    float* psw = ps + warp * 2 * AVS;
    const float scale = 0.17677669529663687f;

    for (int qp = warp; qp < 100; qp += 8) {
        int q0 = qp, q1 = qp + 100;
        float4 qa[8], qb[8];
        const float4* q0p = (const float4*)(Q + base + (size_t)q0 * Dx);
        const float4* q1p = (const float4*)(Q + base + (size_t)q1 * Dx);
#pragma unroll
        for (int i = 0; i < 8; ++i) { qa[i] = q0p[i]; qb[i] = q1p[i]; }

        float s0[7], s1[7], mx0 = -1e30f, mx1 = -1e30f;
#pragma unroll
        for (int j = 0; j < 7; ++j) {
            int k = j * 32 + lane;
            const float* kr = Ks + k * AKS;
            float d0 = 0.f, d1 = 0.f;
#pragma unroll
            for (int i = 0; i < 8; ++i) {
                float4 kv = *(const float4*)(kr + i * 4);
                d0 = fmaf(qa[i].x, kv.x, d0); d0 = fmaf(qa[i].y, kv.y, d0);
                d0 = fmaf(qa[i].z, kv.z, d0); d0 = fmaf(qa[i].w, kv.w, d0);
                d1 = fmaf(qb[i].x, kv.x, d1); d1 = fmaf(qb[i].y, kv.y, d1);
                d1 = fmaf(qb[i].z, kv.z, d1); d1 = fmaf(qb[i].w, kv.w, d1);
            }
            bool valid = (k < 200);
            float fl = valid ? flag[k] : 0.f;
            float v0 = (fl != 0.f) ? d0 * scale : -1e9f;
            float v1 = (fl != 0.f) ? d1 * scale : -1e9f;
            s0[j] = valid ? v0 : -1e30f;
            s1[j] = valid ? v1 : -1e30f;
            mx0 = fmaxf(mx0, s0[j]);
            mx1 = fmaxf(mx1, s1[j]);
        }
#pragma unroll
        for (int o = 16; o; o >>= 1) {
            mx0 = fmaxf(mx0, __shfl_xor_sync(~0u, mx0, o));
            mx1 = fmaxf(mx1, __shfl_xor_sync(~0u, mx1, o));
        }

        float p0[7], p1[7], sum0 = 0.f, sum1 = 0.f;
#pragma unroll
        for (int j = 0; j < 7; ++j) {
            p0[j] = __expf(s0[j] - mx0); sum0 += p0[j];
            p1[j] = __expf(s1[j] - mx1); sum1 += p1[j];
        }
#pragma unroll
        for (int o = 16; o; o >>= 1) {
            sum0 += __shfl_xor_sync(~0u, sum0, o);
            sum1 += __shfl_xor_sync(~0u, sum1, o);
        }
        float inv0 = 1.f / sum0, inv1 = 1.f / sum1;

#pragma unroll
        for (int j = 0; j < 7; ++j) {
            int k = j * 32 + lane;
            if (k < 200) { psw[k] = p0[j]; psw[AVS + k] = p1[j]; }
        }
        __syncwarp();

        float a0 = 0.f, a1 = 0.f;
        const float* vr = Vt + lane * AVS;
#pragma unroll
        for (int kg = 0; kg < 50; ++kg) {
            float4 pv0 = *(const float4*)(psw + kg * 4);
            float4 pv1 = *(const float4*)(psw + AVS + kg * 4);
            float4 vv  = *(const float4*)(vr + kg * 4);
            a0 = fmaf(pv0.x, vv.x, a0); a0 = fmaf(pv0.y, vv.y, a0);
            a0 = fmaf(pv0.z, vv.z, a0); a0 = fmaf(pv0.w, vv.w, a0);
            a1 = fmaf(pv1.x, vv.x, a1); a1 = fmaf(pv1.y, vv.y, a1);
            a1 = fmaf(pv1.z, vv.z, a1); a1 = fmaf(pv1.w, vv.w, a1);
        }
        float vo0 = a0 * inv0, vo1 = a1 * inv1;
        __nv_bfloat16 h0 = __float2bfloat16(vo0), h1 = __float2bfloat16(vo1);
        Oh[base + (size_t)q0 * Dx + lane] = h0;
        Ol[base + (size_t)q0 * Dx + lane] = __float2bfloat16(vo0 - __bfloat162float(h0));
        Oh[base + (size_t)q1 * Dx + lane] = h1;
        Ol[base + (size_t)q1 * Dx + lane] = __float2bfloat16(vo1 - __bfloat162float(h1));
        __syncwarp();
    }
}

// ---------------------------------------------------------------------------
// Host driver (graph-capturable: kernel launches only)
// ---------------------------------------------------------------------------
extern "C" void kernel_launch(void* const* d_in, const int* in_sizes, int n_in,
                              void* d_out, int out_size) {
    (void)in_sizes; (void)n_in; (void)out_size;
    const int*   seqs = (const int*)  d_in[0];
    const float* tok  = (const float*)d_in[1];
    const float* pos  = (const float*)d_in[2];
    const float* Wq   = (const float*)d_in[3];
    const float* bq   = (const float*)d_in[4];
    const float* Wk   = (const float*)d_in[5];
    const float* bk   = (const float*)d_in[6];
    const float* Wv   = (const float*)d_in[7];
    const float* bv   = (const float*)d_in[8];
    const float* Wo   = (const float*)d_in[9];
    const float* bo   = (const float*)d_in[10];
    const float* ln1w = (const float*)d_in[11];
    const float* ln1b = (const float*)d_in[12];
    const float* ln2w = (const float*)d_in[13];
    const float* ln2b = (const float*)d_in[14];
    const float* W1   = (const float*)d_in[15];
    const float* b1   = (const float*)d_in[16];
    const float* W2   = (const float*)d_in[17];
    const float* b2   = (const float*)d_in[18];
    const float* fcW  = (const float*)d_in[19];
    const float* fcb  = (const float*)d_in[20];
    float* out = (float*)d_out;

    float *px, *pq, *pk, *pv, *pp;
    __nv_bfloat16 *ah, *al, *oh, *ol, *fh, *fl, *wh, *wl, *fwh, *fwl;
    cudaGetSymbolAddress((void**)&px, g_x);
    cudaGetSymbolAddress((void**)&pq, g_q);
    cudaGetSymbolAddress((void**)&pk, g_k);
    cudaGetSymbolAddress((void**)&pv, g_v);
    cudaGetSymbolAddress((void**)&pp, g_fcp);
    cudaGetSymbolAddress((void**)&ah, g_ah);
    cudaGetSymbolAddress((void**)&al, g_al);
    cudaGetSymbolAddress((void**)&oh, g_oh);
    cudaGetSymbolAddress((void**)&ol, g_ol);
    cudaGetSymbolAddress((void**)&fh, g_fh);
    cudaGetSymbolAddress((void**)&fl, g_fl);
    cudaGetSymbolAddress((void**)&wh, g_wh);
    cudaGetSymbolAddress((void**)&wl, g_wl);
    cudaGetSymbolAddress((void**)&fwh, g_fcwh);
    cudaGetSymbolAddress((void**)&fwl, g_fcwl);

    cudaFuncSetAttribute(attn_k, cudaFuncAttributeMaxDynamicSharedMemorySize, ATTN_SMEM_BYTES);
    cudaFuncSetAttribute(tgemm<1>, cudaFuncAttributeMaxDynamicSharedMemorySize, TG_SMEM);
    cudaFuncSetAttribute(tgemm<2>, cudaFuncAttributeMaxDynamicSharedMemorySize, TG_SMEM);
    cudaFuncSetAttribute(tgemm<5>, cudaFuncAttributeMaxDynamicSharedMemorySize, TG_SMEM);
    cudaFuncSetAttribute(tgemm_w2, cudaFuncAttributeMaxDynamicSharedMemorySize, W2_SMEM);
    cudaFuncSetAttribute(tgemm_fc, cudaFuncAttributeMaxDynamicSharedMemorySize, W2_SMEM);

    // weight transpose + split
    wconv_all<<<(NLx * LW + 255) / 256, 256>>>(Wq, Wk, Wv, Wo, W1, W2, wh, wl);
    wconv_fc<<<(Dx * FCK + 255) / 256, 256>>>(fcW, fwh, fwl);

    const dim3 gRow(NT / 8);
    const int  MT = NT / 128;  // 1600

    embed_k<<<gRow, 256>>>(seqs, tok, pos, px);

    for (int i = 0; i < NLx; ++i) {
        size_t wb = (size_t)i * LW;
        // --- attention block ---
        ln_k<<<gRow, 256>>>(px, ln1w + i * Dx, ln1b + i * Dx, ah, al);
        tgemm<5><<<dim3(3,148), 256, TG_SMEM>>>(ah, al, Dx, wh + wb, wl + wb,
                 bq + i*Dx, bk + i*Dx, bv + i*Dx, nullptr,
                 pq, pk, pv, nullptr, nullptr, Dx, MT);
        attn_k<<<dim3(Hx, Bx), 256, ATTN_SMEM_BYTES>>>(pq, pk, pv, seqs, oh, ol);
        tgemm<2><<<dim3(1,148), 256, TG_SMEM>>>(oh, ol, Dx, wh + wb + 49152, wl + wb + 49152,
                 bo + i*Dx, nullptr, nullptr, px,
                 px, nullptr, nullptr, nullptr, nullptr, Dx, MT);
        // --- FFN block ---
        ln_k<<<gRow, 256>>>(px, ln2w + i * Dx, ln2b + i * Dx, ah, al);
        tgemm<1><<<dim3(4,37), 256, TG_SMEM>>>(ah, al, Dx, wh + wb + 65536, wl + wb + 65536,
                 b1 + i*FFx, nullptr, nullptr, nullptr,
                 nullptr, nullptr, nullptr, fh, fl, FFx, MT);
        tgemm_w2<<<dim3(1,148), 256, W2_SMEM>>>(fh, fl, wh + wb + 131072, wl + wb + 131072,
                 b2 + i*Dx, px, px, MT);
    }

    // Final FC on tensor path: split x, 25-way K-split partials, reduce.
    xsplit_k<<<(NT * Dx) / 256, 256>>>(px, ah, al);
    tgemm_fc<<<dim3(Bx / 128, FCZ), 256, W2_SMEM>>>(ah, al, fwh, fwl, pp);
    fcred_k<<<(Bx * Dx + 255) / 256, 256>>>(pp, fcb, out);
}